// round 4
// baseline (speedup 1.0000x reference)
#include <cuda_runtime.h>
#include <math.h>

#define NT 49          // tokens per window
#define CDIM 192       // embed dim
#define NH 6           // heads
#define HD 32          // head dim
#define QP 577         // qkv smem row pitch (577 % 32 == 1 -> conflict free)
#define QKV_FLOATS (NT * QP + 3)   // pad to multiple of 4 for 16B alignment of ws
#define WSP 196        // weight tile pitch (floats); 196%32==4 -> conflict-free LDS.128
#define NTHREADS 512
#define SMEM_FLOATS (NT * CDIM + QKV_FLOATS + 64 * WSP)
#define SMEM_BYTES (SMEM_FLOATS * 4)

__global__ void __launch_bounds__(NTHREADS, 1)
wmsa_kernel(const float* __restrict__ x,
            const float* __restrict__ qkv_w,
            const float* __restrict__ qkv_b,
            const float* __restrict__ proj_w,
            const float* __restrict__ proj_b,
            const float* __restrict__ rpe_table,
            const int*   __restrict__ rpe_idx,
            float* __restrict__ out)
{
    extern __shared__ float smem[];
    float* xs   = smem;                    // [49][192] input, later attn output
    float* qkvs = smem + NT * CDIM;        // [49][577] q|k|v per row
    float* ws   = qkvs + QKV_FLOATS;       // [64][196] weight tile (K contiguous)
    int*   rpi  = (int*)ws;                // reuse ws region during attention
    float* rpt  = ws + 2401;

    const int t    = threadIdx.x;
    const int b    = blockIdx.x;
    const int lane = t & 31;
    const int warp = t >> 5;
    const int c    = t & 63;               // column within 64-wide tile
    const int rg   = t >> 6;               // row group 0..7

    // row offsets in float4 units (clamped; stores are guarded)
    int ro[7];
    #pragma unroll
    for (int i = 0; i < 7; i++) {
        int r = rg + 8 * i;
        ro[i] = (r < NT ? r : NT - 1) * (CDIM / 4);
    }

    // ---- load x window tile ----
    {
        const float4* xg = (const float4*)(x + (size_t)b * NT * CDIM);
        float4* x4 = (float4*)xs;
        for (int i = t; i < NT * CDIM / 4; i += NTHREADS) x4[i] = xg[i];
    }

    float4* xs4 = (float4*)xs;
    float4* ws4 = (float4*)ws;

    // ================= Phase 1: QKV = x @ W^T + b =================
    for (int tile = 0; tile < 9; ++tile) {
        __syncthreads();
        // stage 64 rows of qkv_w (each 192 floats), K-contiguous, pitch 196
        const float4* wg = (const float4*)(qkv_w + tile * 64 * CDIM);
        {
            int f = t;
            #pragma unroll
            for (int it = 0; it < 6; ++it, f += NTHREADS) {
                float4 v = wg[f];
                int jj = f / 48;
                int k4 = f - jj * 48;
                ws4[jj * (WSP / 4) + k4] = v;
            }
        }
        __syncthreads();
        const int jc = tile * 64 + c;
        float acc[7];
        {
            float bb = qkv_b[jc];
            #pragma unroll
            for (int i = 0; i < 7; i++) acc[i] = bb;
        }
        #pragma unroll 4
        for (int k4 = 0; k4 < 48; ++k4) {
            float4 wv = ws4[c * (WSP / 4) + k4];
            #pragma unroll
            for (int i = 0; i < 7; i++) {
                float4 xv = xs4[ro[i] + k4];
                acc[i] = fmaf(xv.x, wv.x, acc[i]);
                acc[i] = fmaf(xv.y, wv.y, acc[i]);
                acc[i] = fmaf(xv.z, wv.z, acc[i]);
                acc[i] = fmaf(xv.w, wv.w, acc[i]);
            }
        }
        #pragma unroll
        for (int i = 0; i < 7; i++) {
            int r = rg + 8 * i;
            if (r < NT) qkvs[r * QP + jc] = acc[i];
        }
    }

    // ================= Phase 2: attention =================
    __syncthreads();
    for (int i = t; i < NT * NT; i += NTHREADS) rpi[i] = rpe_idx[i];
    for (int i = t; i < 169 * NH; i += NTHREADS) rpt[i] = rpe_table[i];
    __syncthreads();

    const float scale = 0.17677669529663687f; // 32^-0.5
    for (int task = warp; task < NH * NT; task += NTHREADS / 32) {
        const int h = task / NT;
        const int i = task - h * NT;
        const float* qrow  = qkvs + i * QP + h * HD;
        const float* kcol0 = qkvs + lane * QP + CDIM + h * HD;
        const int j1  = lane + 32;
        const int j1c = (j1 < NT) ? j1 : NT - 1;
        const float* kcol1 = qkvs + j1c * QP + CDIM + h * HD;

        float s0 = 0.f, s1 = 0.f;
        #pragma unroll
        for (int d = 0; d < HD; d += 4) {
            float q0 = qrow[d], q1 = qrow[d + 1], q2 = qrow[d + 2], q3 = qrow[d + 3];
            s0 = fmaf(q0, kcol0[d],     s0);
            s0 = fmaf(q1, kcol0[d + 1], s0);
            s0 = fmaf(q2, kcol0[d + 2], s0);
            s0 = fmaf(q3, kcol0[d + 3], s0);
            s1 = fmaf(q0, kcol1[d],     s1);
            s1 = fmaf(q1, kcol1[d + 1], s1);
            s1 = fmaf(q2, kcol1[d + 2], s1);
            s1 = fmaf(q3, kcol1[d + 3], s1);
        }
        // relative position bias
        float b0 = rpt[rpi[i * NT + lane] * NH + h];
        s0 = s0 * scale + b0;
        if (j1 < NT) {
            float b1 = rpt[rpi[i * NT + j1] * NH + h];
            s1 = s1 * scale + b1;
        } else {
            s1 = -1e30f;
        }
        // softmax over 49 (2 values per lane)
        float m = fmaxf(s0, s1);
        #pragma unroll
        for (int off = 16; off > 0; off >>= 1)
            m = fmaxf(m, __shfl_xor_sync(0xffffffffu, m, off));
        float e0 = __expf(s0 - m);
        float e1 = (j1 < NT) ? __expf(s1 - m) : 0.f;
        float ssum = e0 + e1;
        #pragma unroll
        for (int off = 16; off > 0; off >>= 1)
            ssum += __shfl_xor_sync(0xffffffffu, ssum, off);
        float inv = 1.0f / ssum;
        float p0 = e0 * inv, p1 = e1 * inv;

        // out[i, h, lane] = sum_j p[j] * v[j, lane]
        const float* vcol = qkvs + 2 * CDIM + h * HD + lane;
        float acc = 0.f;
        #pragma unroll
        for (int j = 0; j < 32; j++) {
            float pj = __shfl_sync(0xffffffffu, p0, j);
            acc = fmaf(pj, vcol[j * QP], acc);
        }
        #pragma unroll
        for (int j = 0; j < 17; j++) {
            float pj = __shfl_sync(0xffffffffu, p1, j);
            acc = fmaf(pj, vcol[(j + 32) * QP], acc);
        }
        xs[i * CDIM + h * HD + lane] = acc;   // xs reused as attn-output
    }

    // ================= Phase 3: out = attn_out @ proj_w^T + b =================
    for (int tile = 0; tile < 3; ++tile) {
        __syncthreads();
        const float4* wg = (const float4*)(proj_w + tile * 64 * CDIM);
        {
            int f = t;
            #pragma unroll
            for (int it = 0; it < 6; ++it, f += NTHREADS) {
                float4 v = wg[f];
                int jj = f / 48;
                int k4 = f - jj * 48;
                ws4[jj * (WSP / 4) + k4] = v;
            }
        }
        __syncthreads();
        const int jc = tile * 64 + c;
        float acc[7];
        {
            float bb = proj_b[jc];
            #pragma unroll
            for (int i = 0; i < 7; i++) acc[i] = bb;
        }
        #pragma unroll 4
        for (int k4 = 0; k4 < 48; ++k4) {
            float4 wv = ws4[c * (WSP / 4) + k4];
            #pragma unroll
            for (int i = 0; i < 7; i++) {
                float4 xv = xs4[ro[i] + k4];
                acc[i] = fmaf(xv.x, wv.x, acc[i]);
                acc[i] = fmaf(xv.y, wv.y, acc[i]);
                acc[i] = fmaf(xv.z, wv.z, acc[i]);
                acc[i] = fmaf(xv.w, wv.w, acc[i]);
            }
        }
        float* og = out + (size_t)b * NT * CDIM;
        #pragma unroll
        for (int i = 0; i < 7; i++) {
            int r = rg + 8 * i;
            if (r < NT) og[r * CDIM + jc] = acc[i];
        }
    }
}

extern "C" void kernel_launch(void* const* d_in, const int* in_sizes, int n_in,
                              void* d_out, int out_size)
{
    const float* x         = (const float*)d_in[0];
    const float* qkv_w     = (const float*)d_in[1];
    const float* qkv_b     = (const float*)d_in[2];
    const float* proj_w    = (const float*)d_in[3];
    const float* proj_b    = (const float*)d_in[4];
    const float* rpe_table = (const float*)d_in[5];
    const int*   rpe_idx   = (const int*)d_in[6];
    float* out = (float*)d_out;

    cudaFuncSetAttribute(wmsa_kernel,
                         cudaFuncAttributeMaxDynamicSharedMemorySize, SMEM_BYTES);
    wmsa_kernel<<<4096, NTHREADS, SMEM_BYTES>>>(
        x, qkv_w, qkv_b, proj_w, proj_b, rpe_table, rpe_idx, out);
}

// round 7
// speedup vs baseline: 1.9061x; 1.9061x over previous
#include <cuda_runtime.h>
#include <cuda_fp16.h>
#include <stdint.h>

#define NTHREADS 512
#define AP 400                    // row pitch bytes (200 f16); 100 words == 4 mod 8 -> ldmatrix conflict-free
#define AH_B 0
#define AL_B 44800                // 112*400
#define BH_B 89600
#define BL_B 128000               // BH + 96*400
#define QB_F 22400                // overlays B region (post-MMA)
#define KB_F (QB_F + 98*33)
#define VB_F (KB_F + 98*33)
#define RPI_B 166400
#define RPT_F 42201
#define SB_F (RPT_F + 1014)
#define SMEM_TOTAL (4 * (SB_F + 768) + 4)
#define SCALE 0.17677669529663687f

__device__ float g_ao[2048 * 98 * 192];   // attention-output scratch (allowed: static __device__)

__device__ __forceinline__ uint32_t smem_u32(const void* p) {
    uint32_t a;
    asm("{ .reg .u64 t; cvta.to.shared.u64 t, %1; cvt.u32.u64 %0, t; }" : "=r"(a) : "l"(p));
    return a;
}
__device__ __forceinline__ void ldsm_x4(uint32_t* r, uint32_t a) {
    asm volatile("ldmatrix.sync.aligned.m8n8.x4.shared.b16 {%0,%1,%2,%3}, [%4];"
                 : "=r"(r[0]), "=r"(r[1]), "=r"(r[2]), "=r"(r[3]) : "r"(a));
}
__device__ __forceinline__ void ldsm_x2(uint32_t* r, uint32_t a) {
    asm volatile("ldmatrix.sync.aligned.m8n8.x2.shared.b16 {%0,%1}, [%2];"
                 : "=r"(r[0]), "=r"(r[1]) : "r"(a));
}
__device__ __forceinline__ void mma_step(float* d, const uint32_t* a, const uint32_t* b) {
    asm volatile(
        "mma.sync.aligned.m16n8k16.row.col.f32.f16.f16.f32 "
        "{%0,%1,%2,%3}, {%4,%5,%6,%7}, {%8,%9}, {%0,%1,%2,%3};"
        : "+f"(d[0]), "+f"(d[1]), "+f"(d[2]), "+f"(d[3])
        : "r"(a[0]), "r"(a[1]), "r"(a[2]), "r"(a[3]), "r"(b[0]), "r"(b[1]));
}
__device__ __forceinline__ void mma6(float* acc, const uint32_t* a0, const uint32_t* a1,
                                     const uint32_t* b, const uint32_t* b2) {
    mma_step(acc + 0,  a0, b + 0);
    mma_step(acc + 4,  a0, b + 2);
    mma_step(acc + 8,  a0, b2);
    mma_step(acc + 12, a1, b + 0);
    mma_step(acc + 16, a1, b + 2);
    mma_step(acc + 20, a1, b2);
}
__device__ __forceinline__ void split16(float2 v, __half2& hi, __half2& lo) {
    __half hx = __float2half_rn(v.x), hy = __float2half_rn(v.y);
    hi = __halves2half2(hx, hy);
    lo = __halves2half2(__float2half_rn(v.x - __half2float(hx)),
                        __float2half_rn(v.y - __half2float(hy)));
}

// K=192 (12 k16 steps), 3 passes: Ahi*Bhi + Alo*Bhi + Ahi*Blo
__device__ __forceinline__ void run_gemm(float* acc, uint32_t aaddr, uint32_t baddr, uint32_t b2addr) {
    #pragma unroll
    for (int k = 0; k < 12; k++) {
        uint32_t ah0[4], ah1[4], bh[4], b2[2];
        ldsm_x4(ah0, aaddr);
        ldsm_x4(ah1, aaddr + 16 * AP);
        ldsm_x4(bh, baddr);
        ldsm_x2(b2, b2addr);
        mma6(acc, ah0, ah1, bh, b2);
        uint32_t al0[4], al1[4];
        ldsm_x4(al0, aaddr + (AL_B - AH_B));
        ldsm_x4(al1, aaddr + (AL_B - AH_B) + 16 * AP);
        mma6(acc, al0, al1, bh, b2);
        uint32_t bl[4], bl2[2];
        ldsm_x4(bl, baddr + (BL_B - BH_B));
        ldsm_x2(bl2, b2addr + (BL_B - BH_B));
        mma6(acc, ah0, ah1, bl, bl2);
        aaddr += 32; baddr += 32; b2addr += 32;
    }
}

__global__ void __launch_bounds__(NTHREADS, 1)
wmsa_hmma(const float* __restrict__ x,
          const float* __restrict__ qkv_w,
          const float* __restrict__ qkv_b,
          const float* __restrict__ proj_w,
          const float* __restrict__ proj_b,
          const float* __restrict__ rpe_table,
          const int*   __restrict__ rpe_idx,
          float* __restrict__ out)
{
    extern __shared__ __align__(16) char smem[];
    float* sf = (float*)smem;
    const uint32_t sb = smem_u32(smem);
    const int tid  = threadIdx.x;
    const int warp = tid >> 5;
    const int lane = tid & 31;
    const int wm   = warp >> 2;      // m32-tile 0..3 (rows 32wm..32wm+31)
    const int wn   = warp & 3;       // 24-col slice
    const int bid  = blockIdx.x;     // 2 windows

    // ---- preload bias + rpe ----
    float* sbias = sf + SB_F;
    for (int i = tid; i < 576; i += NTHREADS) sbias[i] = qkv_b[i];
    for (int i = tid; i < 192; i += NTHREADS) sbias[576 + i] = proj_b[i];
    uint8_t* rpi = (uint8_t*)(smem + RPI_B);
    float*   rpt = sf + RPT_F;
    for (int i = tid; i < 49 * 49; i += NTHREADS) rpi[i] = (uint8_t)rpe_idx[i];
    for (int i = tid; i < 169 * 6; i += NTHREADS) rpt[i] = rpe_table[i];

    // ---- zero A (rows 98..111 must be 0), then stage x -> fp16 hi/lo ----
    {
        float4 z = make_float4(0.f, 0.f, 0.f, 0.f);
        float4* a4 = (float4*)smem;
        for (int i = tid; i < 89600 / 16; i += NTHREADS) a4[i] = z;
    }
    __syncthreads();
    {
        const float2* xg = (const float2*)(x + (size_t)bid * 98 * 192);
        for (int idx = tid; idx < 98 * 96; idx += NTHREADS) {
            int r = idx / 96, kp = idx - r * 96;
            __half2 hi, lo;
            split16(xg[idx], hi, lo);
            *(__half2*)(smem + AH_B + r * AP + kp * 4) = hi;
            *(__half2*)(smem + AL_B + r * AP + kp * 4) = lo;
        }
    }

    // ---- per-lane ldmatrix addresses ----
    const uint32_t aaddr = sb + AH_B
        + (uint32_t)(wm * 32 + (lane & 7) + ((lane >> 3) & 1) * 8) * AP
        + (uint32_t)((lane >> 4) * 16);
    const uint32_t baddr = sb + BH_B
        + (uint32_t)(wn * 24 + (lane & 7) + ((lane >> 4) & 1) * 8) * AP
        + (uint32_t)(((lane >> 3) & 1) * 16);
    const int l15 = lane & 15;
    const uint32_t b2addr = sb + BH_B
        + (uint32_t)(wn * 24 + 16 + (l15 & 7)) * AP
        + (uint32_t)((l15 >> 3) * 16);

    float* qb = sf + QB_F;
    float* kb = sf + KB_F;
    float* vb = sf + VB_F;
    float* aog = g_ao + (size_t)bid * 98 * 192;

    // ================= Phase 1+2: per-head GEMM + attention =================
    for (int h = 0; h < 6; h++) {
        // stage B: rows 0-31 = q-slice, 32-63 = k-slice, 64-95 = v-slice of qkv_w
        {
            const float2* wg = (const float2*)qkv_w;
            for (int idx = tid; idx < 96 * 96; idx += NTHREADS) {
                int j = idx / 96, kp = idx - j * 96;
                int grow = (j >> 5) * 192 + h * 32 + (j & 31);
                __half2 hi, lo;
                split16(wg[(size_t)grow * 96 + kp], hi, lo);
                *(__half2*)(smem + BH_B + j * AP + kp * 4) = hi;
                *(__half2*)(smem + BL_B + j * AP + kp * 4) = lo;
            }
        }
        __syncthreads();

        float acc[24];
        #pragma unroll
        for (int i = 0; i < 24; i++) acc[i] = 0.f;
        run_gemm(acc, aaddr, baddr, b2addr);
        __syncthreads();   // all MMA reads of B done before overlaying q/k/v buffers

        // epilogue: route 96 cols -> qb (scaled+bias) / kb (+bias) / vb (+bias)
        #pragma unroll
        for (int t = 0; t < 2; t++) {
            #pragma unroll
            for (int u = 0; u < 3; u++) {
                int r0 = wm * 32 + t * 16 + (lane >> 2);
                int c  = wn * 24 + u * 8 + (lane & 3) * 2;
                int blk = c >> 5, cc = c & 31;
                float bb0 = sbias[blk * 192 + h * 32 + cc];
                float bb1 = sbias[blk * 192 + h * 32 + cc + 1];
                const float* a = acc + t * 12 + u * 4;
                #pragma unroll
                for (int rr = 0; rr < 2; rr++) {
                    int r = r0 + rr * 8;
                    if (r < 98) {
                        float v0 = a[rr * 2 + 0] + bb0;
                        float v1 = a[rr * 2 + 1] + bb1;
                        if (blk == 0)      { qb[r * 33 + cc] = v0 * SCALE; qb[r * 33 + cc + 1] = v1 * SCALE; }
                        else if (blk == 1) { kb[r * 33 + cc] = v0;         kb[r * 33 + cc + 1] = v1; }
                        else               { *(float2*)(vb + r * 32 + cc) = make_float2(v0, v1); }
                    }
                }
            }
        }
        __syncthreads();

        // attention for head h (scalar, fp32) -> global ao
        for (int task = warp; task < 98; task += 16) {
            const int w  = (task >= 49) ? 1 : 0;
            const int i  = task - w * 49;
            const int k0 = w * 49;
            const float* qrow = qb + task * 33;
            const float* kc0  = kb + (k0 + lane) * 33;
            const int j1  = lane + 32;
            const int j1c = (j1 < 49) ? j1 : 48;
            const float* kc1  = kb + (k0 + j1c) * 33;

            float s0 = 0.f, s1 = 0.f;
            #pragma unroll
            for (int d = 0; d < 32; d += 4) {
                float q0 = qrow[d], q1 = qrow[d + 1], q2 = qrow[d + 2], q3 = qrow[d + 3];
                s0 = fmaf(q0, kc0[d], s0);     s0 = fmaf(q1, kc0[d + 1], s0);
                s0 = fmaf(q2, kc0[d + 2], s0); s0 = fmaf(q3, kc0[d + 3], s0);
                s1 = fmaf(q0, kc1[d], s1);     s1 = fmaf(q1, kc1[d + 1], s1);
                s1 = fmaf(q2, kc1[d + 2], s1); s1 = fmaf(q3, kc1[d + 3], s1);
            }
            s0 += rpt[rpi[i * 49 + lane] * 6 + h];
            if (j1 < 49) s1 += rpt[rpi[i * 49 + j1] * 6 + h];
            else         s1 = -1e30f;

            float m = fmaxf(s0, s1);
            #pragma unroll
            for (int off = 16; off > 0; off >>= 1)
                m = fmaxf(m, __shfl_xor_sync(0xffffffffu, m, off));
            float e0 = __expf(s0 - m);
            float e1 = (j1 < 49) ? __expf(s1 - m) : 0.f;
            float ss = e0 + e1;
            #pragma unroll
            for (int off = 16; off > 0; off >>= 1)
                ss += __shfl_xor_sync(0xffffffffu, ss, off);
            float inv = 1.0f / ss;
            float p0 = e0 * inv, p1 = e1 * inv;

            const float* vcol = vb + k0 * 32 + lane;
            float pv = 0.f;
            #pragma unroll
            for (int j = 0; j < 32; j++) {
                float pj = __shfl_sync(0xffffffffu, p0, j);
                pv = fmaf(pj, vcol[j * 32], pv);
            }
            #pragma unroll
            for (int j = 0; j < 17; j++) {
                float pj = __shfl_sync(0xffffffffu, p1, j);
                pv = fmaf(pj, vcol[(j + 32) * 32], pv);
            }
            aog[task * 192 + h * 32 + lane] = pv;
        }
        __syncthreads();   // attention reads of q/k/v done before next head restages B
    }

    // ================= Phase 3: out = ao @ proj_w^T + b =================
    {   // re-split ao into A region (rows 98..111 still zero from init)
        const float2* ag = (const float2*)aog;
        for (int idx = tid; idx < 98 * 96; idx += NTHREADS) {
            int r = idx / 96, kp = idx - r * 96;
            __half2 hi, lo;
            split16(ag[idx], hi, lo);
            *(__half2*)(smem + AH_B + r * AP + kp * 4) = hi;
            *(__half2*)(smem + AL_B + r * AP + kp * 4) = lo;
        }
    }
    for (int s = 0; s < 2; s++) {
        {
            const float2* wg = (const float2*)proj_w;
            for (int idx = tid; idx < 96 * 96; idx += NTHREADS) {
                int j = idx / 96, kp = idx - j * 96;
                __half2 hi, lo;
                split16(wg[(size_t)(s * 96 + j) * 96 + kp], hi, lo);
                *(__half2*)(smem + BH_B + j * AP + kp * 4) = hi;
                *(__half2*)(smem + BL_B + j * AP + kp * 4) = lo;
            }
        }
        __syncthreads();

        float acc[24];
        #pragma unroll
        for (int i = 0; i < 24; i++) acc[i] = 0.f;
        run_gemm(acc, aaddr, baddr, b2addr);

        #pragma unroll
        for (int t = 0; t < 2; t++) {
            #pragma unroll
            for (int u = 0; u < 3; u++) {
                int r0 = wm * 32 + t * 16 + (lane >> 2);
                int c  = wn * 24 + u * 8 + (lane & 3) * 2;
                int gcol = s * 96 + c;
                float bb0 = sbias[576 + gcol];
                float bb1 = sbias[576 + gcol + 1];
                const float* a = acc + t * 12 + u * 4;
                #pragma unroll
                for (int rr = 0; rr < 2; rr++) {
                    int r = r0 + rr * 8;
                    if (r < 98) {
                        float2 v = make_float2(a[rr * 2 + 0] + bb0, a[rr * 2 + 1] + bb1);
                        *(float2*)(out + ((size_t)bid * 98 + r) * 192 + gcol) = v;
                    }
                }
            }
        }
        __syncthreads();   // all MMA done before next stage rewrites B
    }
}

extern "C" void kernel_launch(void* const* d_in, const int* in_sizes, int n_in,
                              void* d_out, int out_size)
{
    const float* x         = (const float*)d_in[0];
    const float* qkv_w     = (const float*)d_in[1];
    const float* qkv_b     = (const float*)d_in[2];
    const float* proj_w    = (const float*)d_in[3];
    const float* proj_b    = (const float*)d_in[4];
    const float* rpe_table = (const float*)d_in[5];
    const int*   rpe_idx   = (const int*)d_in[6];
    float* out = (float*)d_out;

    cudaFuncSetAttribute(wmsa_hmma,
                         cudaFuncAttributeMaxDynamicSharedMemorySize, SMEM_TOTAL);
    wmsa_hmma<<<2048, NTHREADS, SMEM_TOTAL>>>(
        x, qkv_w, qkv_b, proj_w, proj_b, rpe_table, rpe_idx, out);
}

// round 8
// speedup vs baseline: 2.6467x; 1.3885x over previous
#include <cuda_runtime.h>
#include <cuda_fp16.h>
#include <stdint.h>

#define NTHREADS 512
#define AP 400                    // row pitch bytes (200 f16)
#define AH_B 0
#define AL_B 39200                // 98*400
#define BH_B 78400
#define BL_B 116800               // BH + 96*400
#define QB_F 38800                // fp32 q, pitch 36 floats
#define KB_F 42328                // fp32 k, pitch 36
#define VB_F 45856                // fp32 v, pitch 32, 101 rows (3 zero-pad)
#define PB_F 49088                // fp32 p, pitch 52 (cols 49..51 zero)
#define RPI_B 216736
#define RPT_F 54785
#define SBIAS_F 55799
#define SMEM_TOTAL 226304
#define SCALE 0.17677669529663687f

__device__ float g_ao[2048 * 98 * 192];          // attention-output scratch
__device__ __align__(16) char g_wblob[8 * 76800]; // pre-split fp16 hi/lo weights

__device__ __forceinline__ uint32_t smem_u32(const void* p) {
    uint32_t a;
    asm("{ .reg .u64 t; cvta.to.shared.u64 t, %1; cvt.u32.u64 %0, t; }" : "=r"(a) : "l"(p));
    return a;
}
__device__ __forceinline__ void ldsm_x4(uint32_t* r, uint32_t a) {
    asm volatile("ldmatrix.sync.aligned.m8n8.x4.shared.b16 {%0,%1,%2,%3}, [%4];"
                 : "=r"(r[0]), "=r"(r[1]), "=r"(r[2]), "=r"(r[3]) : "r"(a));
}
__device__ __forceinline__ void ldsm_x2(uint32_t* r, uint32_t a) {
    asm volatile("ldmatrix.sync.aligned.m8n8.x2.shared.b16 {%0,%1}, [%2];"
                 : "=r"(r[0]), "=r"(r[1]) : "r"(a));
}
__device__ __forceinline__ void mma_step(float* d, const uint32_t* a, const uint32_t* b) {
    asm volatile(
        "mma.sync.aligned.m16n8k16.row.col.f32.f16.f16.f32 "
        "{%0,%1,%2,%3}, {%4,%5,%6,%7}, {%8,%9}, {%0,%1,%2,%3};"
        : "+f"(d[0]), "+f"(d[1]), "+f"(d[2]), "+f"(d[3])
        : "r"(a[0]), "r"(a[1]), "r"(a[2]), "r"(a[3]), "r"(b[0]), "r"(b[1]));
}
__device__ __forceinline__ void mma6(float* acc, const uint32_t* a0, const uint32_t* a1,
                                     const uint32_t* b, const uint32_t* b2) {
    mma_step(acc + 0,  a0, b + 0);
    mma_step(acc + 4,  a0, b + 2);
    mma_step(acc + 8,  a0, b2);
    mma_step(acc + 12, a1, b + 0);
    mma_step(acc + 16, a1, b + 2);
    mma_step(acc + 20, a1, b2);
}
__device__ __forceinline__ void split16(float2 v, __half2& hi, __half2& lo) {
    __half hx = __float2half_rn(v.x), hy = __float2half_rn(v.y);
    hi = __halves2half2(hx, hy);
    lo = __halves2half2(__float2half_rn(v.x - __half2float(hx)),
                        __float2half_rn(v.y - __half2float(hy)));
}

// K=192 (12 k16 steps), 3 passes: Ahi*Bhi + Alo*Bhi + Ahi*Blo
__device__ __forceinline__ void run_gemm(float* acc, uint32_t aaddr, uint32_t baddr, uint32_t b2addr) {
    #pragma unroll
    for (int k = 0; k < 12; k++) {
        uint32_t ah0[4], ah1[4], bh[4], b2[2];
        ldsm_x4(ah0, aaddr);
        ldsm_x4(ah1, aaddr + 16 * AP);
        ldsm_x4(bh, baddr);
        ldsm_x2(b2, b2addr);
        mma6(acc, ah0, ah1, bh, b2);
        uint32_t al0[4], al1[4];
        ldsm_x4(al0, aaddr + (AL_B - AH_B));
        ldsm_x4(al1, aaddr + (AL_B - AH_B) + 16 * AP);
        mma6(acc, al0, al1, bh, b2);
        uint32_t bl[4], bl2[2];
        ldsm_x4(bl, baddr + (BL_B - BH_B));
        ldsm_x2(bl2, b2addr + (BL_B - BH_B));
        mma6(acc, ah0, ah1, bl, bl2);
        aaddr += 32; baddr += 32; b2addr += 32;
    }
}

// issue cp.async copies of pre-split weight chunk c into B region
__device__ __forceinline__ void stage_chunk(uint32_t sb, int c, int tid) {
    const char* src = g_wblob + (size_t)c * 76800;
    #pragma unroll 1
    for (int i = tid; i < 4800; i += NTHREADS) {
        asm volatile("cp.async.cg.shared.global [%0], [%1], 16;"
                     :: "r"(sb + BH_B + i * 16), "l"(src + (size_t)i * 16));
    }
    asm volatile("cp.async.commit_group;" ::: "memory");
}
#define CPWAIT() asm volatile("cp.async.wait_group 0;" ::: "memory")

// ---------------- prep kernel: split weights to fp16 hi/lo blob ----------------
__global__ void prep_weights(const float* __restrict__ qkv_w, const float* __restrict__ proj_w) {
    int idx = blockIdx.x * 256 + threadIdx.x;      // < 8*96*96 = 73728
    int c  = idx / 9216;
    int r  = idx - c * 9216;
    int j  = r / 96, kp = r - (r / 96) * 96;
    int grow = (c < 6) ? ((j >> 5) * 192 + c * 32 + (j & 31)) : ((c - 6) * 96 + j);
    const float2* src = (c < 6) ? (const float2*)qkv_w : (const float2*)proj_w;
    float2 v = src[(size_t)grow * 96 + kp];
    __half2 hi, lo;
    split16(v, hi, lo);
    char* base = g_wblob + (size_t)c * 76800;
    *(__half2*)(base + j * AP + kp * 4) = hi;
    *(__half2*)(base + 38400 + j * AP + kp * 4) = lo;
}

__global__ void __launch_bounds__(NTHREADS, 1)
wmsa_hmma(const float* __restrict__ x,
          const float* __restrict__ qkv_b,
          const float* __restrict__ proj_b,
          const float* __restrict__ rpe_table,
          const int*   __restrict__ rpe_idx,
          float* __restrict__ out)
{
    extern __shared__ __align__(16) char smem[];
    float* sf = (float*)smem;
    const uint32_t sb = smem_u32(smem);
    const int tid  = threadIdx.x;
    const int warp = tid >> 5;
    const int lane = tid & 31;
    const int wm   = warp >> 2;
    const int wn   = warp & 3;
    const int bid  = blockIdx.x;     // 2 windows

    // ---- preload bias + rpe; zero v pad rows ----
    float* sbias = sf + SBIAS_F;
    for (int i = tid; i < 576; i += NTHREADS) sbias[i] = qkv_b[i];
    for (int i = tid; i < 192; i += NTHREADS) sbias[576 + i] = proj_b[i];
    uint8_t* rpi = (uint8_t*)(smem + RPI_B);
    float*   rpt = sf + RPT_F;
    for (int i = tid; i < 49 * 49; i += NTHREADS) rpi[i] = (uint8_t)rpe_idx[i];
    for (int i = tid; i < 169 * 6; i += NTHREADS) rpt[i] = rpe_table[i];
    if (tid < 96) sf[VB_F + 98 * 32 + tid] = 0.f;   // v rows 98..100 = 0

    // ---- stage x -> fp16 hi/lo into A ----
    {
        const float2* xg = (const float2*)(x + (size_t)bid * 98 * 192);
        for (int idx = tid; idx < 98 * 96; idx += NTHREADS) {
            int r = idx / 96, kp = idx - (idx / 96) * 96;
            __half2 hi, lo;
            split16(xg[idx], hi, lo);
            *(__half2*)(smem + AH_B + r * AP + kp * 4) = hi;
            *(__half2*)(smem + AL_B + r * AP + kp * 4) = lo;
        }
    }
    stage_chunk(sb, 0, tid);   // prefetch head 0's B

    // ---- per-lane ldmatrix addresses ----
    const uint32_t aaddr = sb + AH_B
        + (uint32_t)(wm * 32 + (lane & 7) + ((lane >> 3) & 1) * 8) * AP
        + (uint32_t)((lane >> 4) * 16);
    const uint32_t baddr = sb + BH_B
        + (uint32_t)(wn * 24 + (lane & 7) + ((lane >> 4) & 1) * 8) * AP
        + (uint32_t)(((lane >> 3) & 1) * 16);
    const int l15 = lane & 15;
    const uint32_t b2addr = sb + BH_B
        + (uint32_t)(wn * 24 + 16 + (l15 & 7)) * AP
        + (uint32_t)((l15 >> 3) * 16);

    float* qb = sf + QB_F;
    float* kb = sf + KB_F;
    float* vb = sf + VB_F;
    float* pb = sf + PB_F;
    float* aog = g_ao + (size_t)bid * 98 * 192;

    // ================= Phase 1+2: per-head GEMM + attention =================
    for (int h = 0; h < 6; h++) {
        CPWAIT();
        __syncthreads();                    // B(h) staged & visible; prev overlays free

        float acc[24];
        #pragma unroll
        for (int i = 0; i < 24; i++) acc[i] = 0.f;
        run_gemm(acc, aaddr, baddr, b2addr);
        __syncthreads();                    // all B(h) ldsm reads done

        stage_chunk(sb, h + 1, tid);        // prefetch next chunk under attention

        // epilogue: route 96 cols -> qb(scale+bias) / kb(+bias) / vb(+bias)
        #pragma unroll
        for (int t = 0; t < 2; t++) {
            #pragma unroll
            for (int u = 0; u < 3; u++) {
                int r0e = wm * 32 + t * 16 + (lane >> 2);
                int c   = wn * 24 + u * 8 + (lane & 3) * 2;
                int blk = c >> 5, cc = c & 31;
                float bb0 = sbias[blk * 192 + h * 32 + cc];
                float bb1 = sbias[blk * 192 + h * 32 + cc + 1];
                const float* a = acc + t * 12 + u * 4;
                #pragma unroll
                for (int rr = 0; rr < 2; rr++) {
                    int r = r0e + rr * 8;
                    if (r < 98) {
                        float v0 = a[rr * 2 + 0] + bb0;
                        float v1 = a[rr * 2 + 1] + bb1;
                        if (blk == 0)      { qb[r * 36 + cc] = v0 * SCALE; qb[r * 36 + cc + 1] = v1 * SCALE; }
                        else if (blk == 1) { kb[r * 36 + cc] = v0;         kb[r * 36 + cc + 1] = v1; }
                        else               { *(float2*)(vb + r * 32 + cc) = make_float2(v0, v1); }
                    }
                }
            }
        }
        __syncthreads();

        // ---- attention: row-pair per warp, float4 smem traffic, no PV shuffles ----
        for (int pt = warp; pt < 50; pt += 16) {
            const int w  = (pt >= 25) ? 1 : 0;
            const int p  = pt - w * 25;
            const int i0 = 2 * p;
            const int i1 = (i0 + 1 < 49) ? i0 + 1 : i0;
            const int r0 = w * 49 + i0, r1 = w * 49 + i1;
            const int k0 = w * 49;
            const int j1  = lane + 32;
            const int j1c = (j1 < 49) ? j1 : 48;

            const float4* q0v4 = (const float4*)(sf + QB_F + r0 * 36);
            const float4* q1v4 = (const float4*)(sf + QB_F + r1 * 36);
            const float4* kp0  = (const float4*)(sf + KB_F + (k0 + lane) * 36);
            const float4* kp1  = (const float4*)(sf + KB_F + (k0 + j1c) * 36);

            float s00 = 0.f, s01 = 0.f, s10 = 0.f, s11 = 0.f;
            #pragma unroll
            for (int d4 = 0; d4 < 8; d4++) {
                float4 kv0 = kp0[d4], kv1 = kp1[d4];
                float4 qv0 = q0v4[d4], qv1 = q1v4[d4];
                s00 = fmaf(qv0.x, kv0.x, s00); s00 = fmaf(qv0.y, kv0.y, s00);
                s00 = fmaf(qv0.z, kv0.z, s00); s00 = fmaf(qv0.w, kv0.w, s00);
                s01 = fmaf(qv0.x, kv1.x, s01); s01 = fmaf(qv0.y, kv1.y, s01);
                s01 = fmaf(qv0.z, kv1.z, s01); s01 = fmaf(qv0.w, kv1.w, s01);
                s10 = fmaf(qv1.x, kv0.x, s10); s10 = fmaf(qv1.y, kv0.y, s10);
                s10 = fmaf(qv1.z, kv0.z, s10); s10 = fmaf(qv1.w, kv0.w, s10);
                s11 = fmaf(qv1.x, kv1.x, s11); s11 = fmaf(qv1.y, kv1.y, s11);
                s11 = fmaf(qv1.z, kv1.z, s11); s11 = fmaf(qv1.w, kv1.w, s11);
            }
            const uint8_t* rpi0 = rpi + i0 * 49;
            const uint8_t* rpi1 = rpi + i1 * 49;
            s00 += rpt[rpi0[lane] * 6 + h];
            s10 += rpt[rpi1[lane] * 6 + h];
            if (j1 < 49) { s01 += rpt[rpi0[j1] * 6 + h]; s11 += rpt[rpi1[j1] * 6 + h]; }
            else         { s01 = -1e30f; s11 = -1e30f; }

            float m0 = fmaxf(s00, s01), m1 = fmaxf(s10, s11);
            #pragma unroll
            for (int o = 16; o > 0; o >>= 1) {
                m0 = fmaxf(m0, __shfl_xor_sync(0xffffffffu, m0, o));
                m1 = fmaxf(m1, __shfl_xor_sync(0xffffffffu, m1, o));
            }
            float e00 = __expf(s00 - m0), e01 = (j1 < 49) ? __expf(s01 - m0) : 0.f;
            float e10 = __expf(s10 - m1), e11 = (j1 < 49) ? __expf(s11 - m1) : 0.f;
            float t0 = e00 + e01, t1 = e10 + e11;
            #pragma unroll
            for (int o = 16; o > 0; o >>= 1) {
                t0 += __shfl_xor_sync(0xffffffffu, t0, o);
                t1 += __shfl_xor_sync(0xffffffffu, t1, o);
            }
            float iv0 = 1.0f / t0, iv1 = 1.0f / t1;
            pb[r0 * 52 + lane] = e00 * iv0;
            pb[r1 * 52 + lane] = e10 * iv1;
            if (j1 < 52) {                     // cols 49..51 store 0 (e=0)
                pb[r0 * 52 + j1] = e01 * iv0;
                pb[r1 * 52 + j1] = e11 * iv1;
            }
            __syncwarp();

            const float4* pr0 = (const float4*)(sf + PB_F + r0 * 52);
            const float4* pr1 = (const float4*)(sf + PB_F + r1 * 52);
            const float* vc = vb + k0 * 32 + lane;
            float a0 = 0.f, a1 = 0.f, c0 = 0.f, c1 = 0.f;
            #pragma unroll
            for (int j4 = 0; j4 < 13; j4++) {
                float4 p0v = pr0[j4], p1v = pr1[j4];
                float v0 = vc[(4 * j4 + 0) * 32], v1 = vc[(4 * j4 + 1) * 32];
                float v2 = vc[(4 * j4 + 2) * 32], v3 = vc[(4 * j4 + 3) * 32];
                a0 = fmaf(p0v.x, v0, a0); c0 = fmaf(p0v.y, v1, c0);
                a0 = fmaf(p0v.z, v2, a0); c0 = fmaf(p0v.w, v3, c0);
                a1 = fmaf(p1v.x, v0, a1); c1 = fmaf(p1v.y, v1, c1);
                a1 = fmaf(p1v.z, v2, a1); c1 = fmaf(p1v.w, v3, c1);
            }
            aog[r0 * 192 + h * 32 + lane] = a0 + c0;
            aog[r1 * 192 + h * 32 + lane] = a1 + c1;
        }
    }
    __syncthreads();   // all aog writes visible

    // ================= Phase 3: out = ao @ proj_w^T + b =================
    {   // re-split ao into A region
        const float2* ag = (const float2*)aog;
        for (int idx = tid; idx < 98 * 96; idx += NTHREADS) {
            int r = idx / 96, kp = idx - (idx / 96) * 96;
            __half2 hi, lo;
            split16(ag[idx], hi, lo);
            *(__half2*)(smem + AH_B + r * AP + kp * 4) = hi;
            *(__half2*)(smem + AL_B + r * AP + kp * 4) = lo;
        }
    }
    for (int s = 0; s < 2; s++) {
        CPWAIT();
        __syncthreads();

        float acc[24];
        #pragma unroll
        for (int i = 0; i < 24; i++) acc[i] = 0.f;
        run_gemm(acc, aaddr, baddr, b2addr);
        __syncthreads();
        if (s == 0) stage_chunk(sb, 7, tid);

        #pragma unroll
        for (int t = 0; t < 2; t++) {
            #pragma unroll
            for (int u = 0; u < 3; u++) {
                int r0e = wm * 32 + t * 16 + (lane >> 2);
                int c   = wn * 24 + u * 8 + (lane & 3) * 2;
                int gcol = s * 96 + c;
                float bb0 = sbias[576 + gcol];
                float bb1 = sbias[576 + gcol + 1];
                const float* a = acc + t * 12 + u * 4;
                #pragma unroll
                for (int rr = 0; rr < 2; rr++) {
                    int r = r0e + rr * 8;
                    if (r < 98) {
                        float2 v = make_float2(a[rr * 2 + 0] + bb0, a[rr * 2 + 1] + bb1);
                        *(float2*)(out + ((size_t)bid * 98 + r) * 192 + gcol) = v;
                    }
                }
            }
        }
    }
}

extern "C" void kernel_launch(void* const* d_in, const int* in_sizes, int n_in,
                              void* d_out, int out_size)
{
    const float* x         = (const float*)d_in[0];
    const float* qkv_w     = (const float*)d_in[1];
    const float* qkv_b     = (const float*)d_in[2];
    const float* proj_w    = (const float*)d_in[3];
    const float* proj_b    = (const float*)d_in[4];
    const float* rpe_table = (const float*)d_in[5];
    const int*   rpe_idx   = (const int*)d_in[6];
    float* out = (float*)d_out;

    prep_weights<<<288, 256>>>(qkv_w, proj_w);

    cudaFuncSetAttribute(wmsa_hmma,
                         cudaFuncAttributeMaxDynamicSharedMemorySize, SMEM_TOTAL);
    wmsa_hmma<<<2048, NTHREADS, SMEM_TOTAL>>>(
        x, qkv_b, proj_b, rpe_table, rpe_idx, out);
}

// round 12
// speedup vs baseline: 3.6688x; 1.3862x over previous
#include <cuda_runtime.h>
#include <cuda_fp16.h>
#include <stdint.h>

#define NTHREADS 512
#define AP 400                    // A/B row pitch bytes (200 f16)
#define AH_B 0
#define AL_B 39200                // 98*400
#define BH_B 78400
#define BL_B 116800
// fp16 attention images
#define QI_B 155200               // 120 rows x 80B (40 halfs)
#define KI_B 164800
#define VTH_B 174400              // per win: 32 dims x 144B = 4608B; 2 windows = 9216B
#define VT_WIN 4608
#define VTL_B 183616
#define RPI_B 192832              // 2401 bytes
#define RPT_F 48809               // float idx (byte 195236)
#define SBIAS_F 49823             // float idx (byte 199292)
#define SMEM_TOTAL 202368
#define SCALE 0.17677669529663687f

__device__ float g_ao[2048 * 98 * 192];           // attention-output scratch
__device__ __align__(16) char g_wblob[8 * 76800]; // pre-split fp16 hi/lo weights

__device__ __forceinline__ uint32_t smem_u32(const void* p) {
    uint32_t a;
    asm("{ .reg .u64 t; cvta.to.shared.u64 t, %1; cvt.u32.u64 %0, t; }" : "=r"(a) : "l"(p));
    return a;
}
__device__ __forceinline__ uint32_t pack_h2(__half lo, __half hi) {
    return (uint32_t)__half_as_ushort(lo) | ((uint32_t)__half_as_ushort(hi) << 16);
}
__device__ __forceinline__ void ldsm_x4(uint32_t* r, uint32_t a) {
    asm volatile("ldmatrix.sync.aligned.m8n8.x4.shared.b16 {%0,%1,%2,%3}, [%4];"
                 : "=r"(r[0]), "=r"(r[1]), "=r"(r[2]), "=r"(r[3]) : "r"(a));
}
__device__ __forceinline__ void ldsm_x2(uint32_t* r, uint32_t a) {
    asm volatile("ldmatrix.sync.aligned.m8n8.x2.shared.b16 {%0,%1}, [%2];"
                 : "=r"(r[0]), "=r"(r[1]) : "r"(a));
}
__device__ __forceinline__ void mma_step(float* d, const uint32_t* a, const uint32_t* b) {
    asm volatile(
        "mma.sync.aligned.m16n8k16.row.col.f32.f16.f16.f32 "
        "{%0,%1,%2,%3}, {%4,%5,%6,%7}, {%8,%9}, {%0,%1,%2,%3};"
        : "+f"(d[0]), "+f"(d[1]), "+f"(d[2]), "+f"(d[3])
        : "r"(a[0]), "r"(a[1]), "r"(a[2]), "r"(a[3]), "r"(b[0]), "r"(b[1]));
}
__device__ __forceinline__ void mma6(float* acc, const uint32_t* a0, const uint32_t* a1,
                                     const uint32_t* b, const uint32_t* b2) {
    mma_step(acc + 0,  a0, b + 0);
    mma_step(acc + 4,  a0, b + 2);
    mma_step(acc + 8,  a0, b2);
    mma_step(acc + 12, a1, b + 0);
    mma_step(acc + 16, a1, b + 2);
    mma_step(acc + 20, a1, b2);
}
__device__ __forceinline__ void split16(float2 v, __half2& hi, __half2& lo) {
    __half hx = __float2half_rn(v.x), hy = __float2half_rn(v.y);
    hi = __halves2half2(hx, hy);
    lo = __halves2half2(__float2half_rn(v.x - __half2float(hx)),
                        __float2half_rn(v.y - __half2float(hy)));
}

// K=192 GEMM, 3 passes: Ahi*Bhi + Alo*Bhi + Ahi*Blo
__device__ __forceinline__ void run_gemm(float* acc, uint32_t aaddr, uint32_t baddr, uint32_t b2addr) {
    #pragma unroll
    for (int k = 0; k < 12; k++) {
        uint32_t ah0[4], ah1[4], bh[4], b2[2];
        ldsm_x4(ah0, aaddr);
        ldsm_x4(ah1, aaddr + 16 * AP);
        ldsm_x4(bh, baddr);
        ldsm_x2(b2, b2addr);
        mma6(acc, ah0, ah1, bh, b2);
        uint32_t al0[4], al1[4];
        ldsm_x4(al0, aaddr + (AL_B - AH_B));
        ldsm_x4(al1, aaddr + (AL_B - AH_B) + 16 * AP);
        mma6(acc, al0, al1, bh, b2);
        uint32_t bl[4], bl2[2];
        ldsm_x4(bl, baddr + (BL_B - BH_B));
        ldsm_x2(bl2, b2addr + (BL_B - BH_B));
        mma6(acc, ah0, ah1, bl, bl2);
        aaddr += 32; baddr += 32; b2addr += 32;
    }
}

__device__ __forceinline__ void stage_chunk(uint32_t sb, int c, int tid) {
    const char* src = g_wblob + (size_t)c * 76800;
    #pragma unroll 1
    for (int i = tid; i < 4800; i += NTHREADS) {
        asm volatile("cp.async.cg.shared.global [%0], [%1], 16;"
                     :: "r"(sb + BH_B + i * 16), "l"(src + (size_t)i * 16));
    }
    asm volatile("cp.async.commit_group;" ::: "memory");
}
#define CPWAIT() asm volatile("cp.async.wait_group 0;" ::: "memory")

__global__ void prep_weights(const float* __restrict__ qkv_w, const float* __restrict__ proj_w) {
    int idx = blockIdx.x * 256 + threadIdx.x;      // < 8*96*96 = 73728
    int c  = idx / 9216;
    int r  = idx - c * 9216;
    int j  = r / 96, kp = r - (r / 96) * 96;
    int grow = (c < 6) ? ((j >> 5) * 192 + c * 32 + (j & 31)) : ((c - 6) * 96 + j);
    const float2* src = (c < 6) ? (const float2*)qkv_w : (const float2*)proj_w;
    float2 v = src[(size_t)grow * 96 + kp];
    __half2 hi, lo;
    split16(v, hi, lo);
    char* base = g_wblob + (size_t)c * 76800;
    *(__half2*)(base + j * AP + kp * 4) = hi;
    *(__half2*)(base + 38400 + j * AP + kp * 4) = lo;
}

__global__ void __launch_bounds__(NTHREADS, 1)
wmsa_hmma(const float* __restrict__ x,
          const float* __restrict__ qkv_b,
          const float* __restrict__ proj_b,
          const float* __restrict__ rpe_table,
          const int*   __restrict__ rpe_idx,
          float* __restrict__ out)
{
    extern __shared__ __align__(16) char smem[];
    float* sf = (float*)smem;
    const uint32_t sb = smem_u32(smem);
    const int tid  = threadIdx.x;
    const int warp = tid >> 5;
    const int lane = tid & 31;
    const int wm   = warp >> 2;
    const int wn   = warp & 3;
    const int bid  = blockIdx.x;     // 2 windows

    // ---- preload bias + rpe; zero q/k pad rows + vt images ----
    float* sbias = sf + SBIAS_F;
    for (int i = tid; i < 576; i += NTHREADS) sbias[i] = qkv_b[i];
    for (int i = tid; i < 192; i += NTHREADS) sbias[576 + i] = proj_b[i];
    uint8_t* rpi = (uint8_t*)(smem + RPI_B);
    float*   rpt = sf + RPT_F;
    for (int i = tid; i < 49 * 49; i += NTHREADS) rpi[i] = (uint8_t)rpe_idx[i];
    for (int i = tid; i < 169 * 6; i += NTHREADS) rpt[i] = rpe_table[i];
    {   // zero q/k rows 98..119 (2x1760B) and full vt hi+lo (18432B)
        uint32_t* z1 = (uint32_t*)(smem + QI_B + 98 * 80);
        uint32_t* z2 = (uint32_t*)(smem + KI_B + 98 * 80);
        for (int i = tid; i < 440; i += NTHREADS) { z1[i] = 0u; z2[i] = 0u; }
        uint32_t* z3 = (uint32_t*)(smem + VTH_B);
        for (int i = tid; i < 4608; i += NTHREADS) z3[i] = 0u;
    }

    // ---- stage x -> fp16 hi/lo into A ----
    {
        const float2* xg = (const float2*)(x + (size_t)bid * 98 * 192);
        for (int idx = tid; idx < 98 * 96; idx += NTHREADS) {
            int r = idx / 96, kp = idx - (idx / 96) * 96;
            __half2 hi, lo;
            split16(xg[idx], hi, lo);
            *(__half2*)(smem + AH_B + r * AP + kp * 4) = hi;
            *(__half2*)(smem + AL_B + r * AP + kp * 4) = lo;
        }
    }
    stage_chunk(sb, 0, tid);

    // ---- GEMM ldmatrix addresses ----
    const uint32_t aaddr = sb + AH_B
        + (uint32_t)(wm * 32 + (lane & 7) + ((lane >> 3) & 1) * 8) * AP
        + (uint32_t)((lane >> 4) * 16);
    const uint32_t baddr = sb + BH_B
        + (uint32_t)(wn * 24 + (lane & 7) + ((lane >> 4) & 1) * 8) * AP
        + (uint32_t)(((lane >> 3) & 1) * 16);
    const int l15 = lane & 15;
    const uint32_t b2addr = sb + BH_B
        + (uint32_t)(wn * 24 + 16 + (l15 & 7)) * AP
        + (uint32_t)((l15 >> 3) * 16);

    // ---- attention warp geometry ----
    const int mt  = warp & 7;        // m16 tile: window*4 + tm
    const int win = mt >> 2;
    const int tm  = mt & 3;
    const int nh  = warp >> 3;       // dim half 0/1
    const int qr  = lane >> 2;       // quad row
    const int qc  = (lane & 3) * 2;  // quad col base
    const int iA  = tm * 16 + qr;    // local row within window (0..63)
    const int iB  = iA + 8;
    const int iAc = (iA < 49 ? iA : 48) * 49;
    const int iBc = (iB < 49 ? iB : 48) * 49;
    const uint32_t qaddr = sb + QI_B
        + (uint32_t)(win * 49 + tm * 16 + (lane & 7) + ((lane >> 3) & 1) * 8) * 80
        + (uint32_t)((lane >> 4) * 16);
    const uint32_t kaddr0 = sb + KI_B
        + (uint32_t)(win * 49 + (lane & 7) + (lane >> 4) * 8) * 80
        + (uint32_t)(((lane >> 3) & 1) * 16);
    const uint32_t vtaddr = sb + VTH_B + (uint32_t)(win * VT_WIN)
        + (uint32_t)(nh * 16 + (lane & 7) + (lane >> 4) * 8) * 144
        + (uint32_t)(((lane >> 3) & 1) * 16);

    float* aog = g_ao + (size_t)bid * 98 * 192;

    // ================= Phase 1+2: per-head GEMM + HMMA attention =================
    for (int h = 0; h < 6; h++) {
        CPWAIT();
        __syncthreads();                 // B(h) staged; prior attention reads done

        float acc[24];
        #pragma unroll
        for (int i = 0; i < 24; i++) acc[i] = 0.f;
        run_gemm(acc, aaddr, baddr, b2addr);
        __syncthreads();                 // B(h) ldsm reads done

        stage_chunk(sb, h + 1, tid);     // prefetch next chunk under epilogue+attention

        // epilogue: q/k -> fp16 images (+bias, q scaled); v -> transposed fp16 hi/lo
        #pragma unroll
        for (int t = 0; t < 2; t++) {
            #pragma unroll
            for (int u = 0; u < 3; u++) {
                int r0e = wm * 32 + t * 16 + (lane >> 2);
                int c   = wn * 24 + u * 8 + (lane & 3) * 2;
                int blk = c >> 5, cc = c & 31;
                float bb0 = sbias[blk * 192 + h * 32 + cc];
                float bb1 = sbias[blk * 192 + h * 32 + cc + 1];
                const float* a = acc + t * 12 + u * 4;
                #pragma unroll
                for (int rr = 0; rr < 2; rr++) {
                    int r = r0e + rr * 8;
                    if (r < 98) {
                        float v0 = a[rr * 2 + 0] + bb0;
                        float v1 = a[rr * 2 + 1] + bb1;
                        if (blk == 0) {
                            *(__half2*)(smem + QI_B + r * 80 + cc * 2) =
                                __floats2half2_rn(v0 * SCALE, v1 * SCALE);
                        } else if (blk == 1) {
                            *(__half2*)(smem + KI_B + r * 80 + cc * 2) =
                                __floats2half2_rn(v0, v1);
                        } else {
                            int w2 = (r >= 49);
                            int key = r - w2 * 49;
                            __half h0 = __float2half_rn(v0);
                            __half h1 = __float2half_rn(v1);
                            char* vh = smem + VTH_B + w2 * VT_WIN + key * 2;
                            char* vl = smem + VTL_B + w2 * VT_WIN + key * 2;
                            *(__half*)(vh + cc * 144)       = h0;
                            *(__half*)(vh + (cc + 1) * 144) = h1;
                            *(__half*)(vl + cc * 144)       = __float2half_rn(v0 - __half2float(h0));
                            *(__half*)(vl + (cc + 1) * 144) = __float2half_rn(v1 - __half2float(h1));
                        }
                    }
                }
            }
        }
        __syncthreads();                 // q/k/vt images ready

        // ---- S = Q K^T (fragments) ----
        float s[7][4];
        #pragma unroll
        for (int i = 0; i < 7; i++) { s[i][0] = s[i][1] = s[i][2] = s[i][3] = 0.f; }
        uint32_t a0[4], a1[4];
        ldsm_x4(a0, qaddr);
        ldsm_x4(a1, qaddr + 32);
        #pragma unroll
        for (int t16 = 0; t16 < 4; t16++) {
            uint32_t b0[4], b1[4];
            uint32_t ka = kaddr0 + (uint32_t)(t16 * 16) * 80;
            ldsm_x4(b0, ka);
            ldsm_x4(b1, ka + 32);
            mma_step(s[2 * t16], a0, b0 + 0);
            mma_step(s[2 * t16], a1, b1 + 0);
            if (t16 < 3) {
                mma_step(s[2 * t16 + 1], a0, b0 + 2);
                mma_step(s[2 * t16 + 1], a1, b1 + 2);
            }
        }

        // ---- bias + mask + softmax in fragments ----
        float mx0 = -1e30f, mx1 = -1e30f;
        #pragma unroll
        for (int t = 0; t < 7; t++) {
            int c0 = t * 8 + qc, c1 = c0 + 1;
            if (c0 < 49) { s[t][0] += rpt[rpi[iAc + c0] * 6 + h]; s[t][2] += rpt[rpi[iBc + c0] * 6 + h]; }
            else         { s[t][0] = -1e30f; s[t][2] = -1e30f; }
            if (c1 < 49) { s[t][1] += rpt[rpi[iAc + c1] * 6 + h]; s[t][3] += rpt[rpi[iBc + c1] * 6 + h]; }
            else         { s[t][1] = -1e30f; s[t][3] = -1e30f; }
            mx0 = fmaxf(mx0, fmaxf(s[t][0], s[t][1]));
            mx1 = fmaxf(mx1, fmaxf(s[t][2], s[t][3]));
        }
        mx0 = fmaxf(mx0, __shfl_xor_sync(0xffffffffu, mx0, 1));
        mx0 = fmaxf(mx0, __shfl_xor_sync(0xffffffffu, mx0, 2));
        mx1 = fmaxf(mx1, __shfl_xor_sync(0xffffffffu, mx1, 1));
        mx1 = fmaxf(mx1, __shfl_xor_sync(0xffffffffu, mx1, 2));
        float sm0 = 0.f, sm1 = 0.f;
        #pragma unroll
        for (int t = 0; t < 7; t++) {
            s[t][0] = __expf(s[t][0] - mx0); s[t][1] = __expf(s[t][1] - mx0);
            s[t][2] = __expf(s[t][2] - mx1); s[t][3] = __expf(s[t][3] - mx1);
            sm0 += s[t][0] + s[t][1];
            sm1 += s[t][2] + s[t][3];
        }
        sm0 += __shfl_xor_sync(0xffffffffu, sm0, 1);
        sm0 += __shfl_xor_sync(0xffffffffu, sm0, 2);
        sm1 += __shfl_xor_sync(0xffffffffu, sm1, 1);
        sm1 += __shfl_xor_sync(0xffffffffu, sm1, 2);
        float iv0 = 1.0f / sm0, iv1 = 1.0f / sm1;

        // ---- P fragments (hi/lo), accumulator layout == A-fragment layout ----
        uint32_t phi[4][4], plo[4][4];
        #pragma unroll
        for (int kc = 0; kc < 4; kc++) {
            #pragma unroll
            for (int h2i = 0; h2i < 4; h2i++) {
                int t = 2 * kc + (h2i >> 1);         // even tile for regs 0-1; odd tile for regs 2-3
                int rsel = (h2i & 1) * 2;            // 0 -> rowA regs, 2 -> rowB regs
                float p0, p1;
                if (t < 7) {
                    float ivx = (h2i & 1) ? iv1 : iv0;
                    p0 = s[t][rsel + 0] * ivx;
                    p1 = s[t][rsel + 1] * ivx;
                } else { p0 = 0.f; p1 = 0.f; }
                __half hp0 = __float2half_rn(p0), hp1 = __float2half_rn(p1);
                phi[kc][h2i] = pack_h2(hp0, hp1);
                plo[kc][h2i] = pack_h2(__float2half_rn(p0 - __half2float(hp0)),
                                       __float2half_rn(p1 - __half2float(hp1)));
            }
        }

        // ---- PV: 3-pass (Phi*Vhi + Plo*Vhi + Phi*Vlo) ----
        float o0[4] = {0.f, 0.f, 0.f, 0.f};
        float o1[4] = {0.f, 0.f, 0.f, 0.f};
        #pragma unroll
        for (int kc = 0; kc < 4; kc++) {
            uint32_t vh[4], vl[4];
            uint32_t va = vtaddr + (uint32_t)(kc * 32);
            ldsm_x4(vh, va);
            ldsm_x4(vl, va + (VTL_B - VTH_B));
            mma_step(o0, phi[kc], vh + 0);
            mma_step(o1, phi[kc], vh + 2);
            mma_step(o0, plo[kc], vh + 0);
            mma_step(o1, plo[kc], vh + 2);
            mma_step(o0, phi[kc], vl + 0);
            mma_step(o1, phi[kc], vl + 2);
        }

        // ---- store ao rows ----
        {
            int dn = h * 32 + nh * 16 + qc;
            if (iA < 49) {
                float* dst = aog + (win * 49 + iA) * 192 + dn;
                *(float2*)(dst)     = make_float2(o0[0], o0[1]);
                *(float2*)(dst + 8) = make_float2(o1[0], o1[1]);
            }
            if (iB < 49) {
                float* dst = aog + (win * 49 + iB) * 192 + dn;
                *(float2*)(dst)     = make_float2(o0[2], o0[3]);
                *(float2*)(dst + 8) = make_float2(o1[2], o1[3]);
            }
        }
    }
    __syncthreads();   // all aog writes visible

    // ================= Phase 3: out = ao @ proj_w^T + b =================
    {   // re-split ao into A region
        const float2* ag = (const float2*)aog;
        for (int idx = tid; idx < 98 * 96; idx += NTHREADS) {
            int r = idx / 96, kp = idx - (idx / 96) * 96;
            __half2 hi, lo;
            split16(ag[idx], hi, lo);
            *(__half2*)(smem + AH_B + r * AP + kp * 4) = hi;
            *(__half2*)(smem + AL_B + r * AP + kp * 4) = lo;
        }
    }
    for (int s2 = 0; s2 < 2; s2++) {
        CPWAIT();
        __syncthreads();

        float acc[24];
        #pragma unroll
        for (int i = 0; i < 24; i++) acc[i] = 0.f;
        run_gemm(acc, aaddr, baddr, b2addr);
        __syncthreads();
        if (s2 == 0) stage_chunk(sb, 7, tid);

        #pragma unroll
        for (int t = 0; t < 2; t++) {
            #pragma unroll
            for (int u = 0; u < 3; u++) {
                int r0e = wm * 32 + t * 16 + (lane >> 2);
                int c   = wn * 24 + u * 8 + (lane & 3) * 2;
                int gcol = s2 * 96 + c;
                float bb0 = sbias[576 + gcol];
                float bb1 = sbias[576 + gcol + 1];
                const float* a = acc + t * 12 + u * 4;
                #pragma unroll
                for (int rr = 0; rr < 2; rr++) {
                    int r = r0e + rr * 8;
                    if (r < 98) {
                        float2 v = make_float2(a[rr * 2 + 0] + bb0, a[rr * 2 + 1] + bb1);
                        *(float2*)(out + ((size_t)bid * 98 + r) * 192 + gcol) = v;
                    }
                }
            }
        }
    }
}

extern "C" void kernel_launch(void* const* d_in, const int* in_sizes, int n_in,
                              void* d_out, int out_size)
{
    const float* x         = (const float*)d_in[0];
    const float* qkv_w     = (const float*)d_in[1];
    const float* qkv_b     = (const float*)d_in[2];
    const float* proj_w    = (const float*)d_in[3];
    const float* proj_b    = (const float*)d_in[4];
    const float* rpe_table = (const float*)d_in[5];
    const int*   rpe_idx   = (const int*)d_in[6];
    float* out = (float*)d_out;

    prep_weights<<<288, 256>>>(qkv_w, proj_w);

    cudaFuncSetAttribute(wmsa_hmma,
                         cudaFuncAttributeMaxDynamicSharedMemorySize, SMEM_TOTAL);
    wmsa_hmma<<<2048, NTHREADS, SMEM_TOTAL>>>(
        x, qkv_b, proj_b, rpe_table, rpe_idx, out);
}

// round 14
// speedup vs baseline: 4.5695x; 1.2455x over previous
#include <cuda_runtime.h>
#include <cuda_fp16.h>
#include <stdint.h>

#define NTHREADS 512
#define AP 400                    // A/B row pitch bytes (200 f16)
#define AH_B 0                    // 98 x 400
#define AL_B 39200                // 98 x 400
#define B_B  78400                // 96 x 400 (hi only)
#define QI_B 116800               // 120 rows x 80B
#define KI_B 126400               // 120 rows x 80B
#define VTH_B 136000              // per win: 32 dims x 144B = 4608B; 2 windows
#define VT_WIN 4608
#define RPI_B 145216              // 2401 bytes
#define RPT_F 36905               // float idx (byte 147620), 1014 floats
#define SBIAS_F 37919             // float idx (byte 151676), 768 floats
#define SMEM_TOTAL 154752
#define SCALE 0.17677669529663687f

__device__ __align__(16) char g_ao[2048 * 78400];   // ao as fp16 hi|lo in A-image layout
__device__ __align__(16) char g_wblob[8 * 38400];   // pre-split fp16 hi weights

__device__ __forceinline__ uint32_t smem_u32(const void* p) {
    uint32_t a;
    asm("{ .reg .u64 t; cvta.to.shared.u64 t, %1; cvt.u32.u64 %0, t; }" : "=r"(a) : "l"(p));
    return a;
}
__device__ __forceinline__ uint32_t pack_h2(__half lo, __half hi) {
    return (uint32_t)__half_as_ushort(lo) | ((uint32_t)__half_as_ushort(hi) << 16);
}
__device__ __forceinline__ void ldsm_x4(uint32_t* r, uint32_t a) {
    asm volatile("ldmatrix.sync.aligned.m8n8.x4.shared.b16 {%0,%1,%2,%3}, [%4];"
                 : "=r"(r[0]), "=r"(r[1]), "=r"(r[2]), "=r"(r[3]) : "r"(a));
}
__device__ __forceinline__ void ldsm_x2(uint32_t* r, uint32_t a) {
    asm volatile("ldmatrix.sync.aligned.m8n8.x2.shared.b16 {%0,%1}, [%2];"
                 : "=r"(r[0]), "=r"(r[1]) : "r"(a));
}
__device__ __forceinline__ void mma_step(float* d, const uint32_t* a, const uint32_t* b) {
    asm volatile(
        "mma.sync.aligned.m16n8k16.row.col.f32.f16.f16.f32 "
        "{%0,%1,%2,%3}, {%4,%5,%6,%7}, {%8,%9}, {%0,%1,%2,%3};"
        : "+f"(d[0]), "+f"(d[1]), "+f"(d[2]), "+f"(d[3])
        : "r"(a[0]), "r"(a[1]), "r"(a[2]), "r"(a[3]), "r"(b[0]), "r"(b[1]));
}
__device__ __forceinline__ void mma6(float* acc, const uint32_t* a0, const uint32_t* a1,
                                     const uint32_t* b, const uint32_t* b2) {
    mma_step(acc + 0,  a0, b + 0);
    mma_step(acc + 4,  a0, b + 2);
    mma_step(acc + 8,  a0, b2);
    mma_step(acc + 12, a1, b + 0);
    mma_step(acc + 16, a1, b + 2);
    mma_step(acc + 20, a1, b2);
}
__device__ __forceinline__ void split16(float2 v, __half2& hi, __half2& lo) {
    __half hx = __float2half_rn(v.x), hy = __float2half_rn(v.y);
    hi = __halves2half2(hx, hy);
    lo = __halves2half2(__float2half_rn(v.x - __half2float(hx)),
                        __float2half_rn(v.y - __half2float(hy)));
}

// K=192 GEMM, 2 passes: (Ahi + Alo) * Bhi
__device__ __forceinline__ void run_gemm(float* acc, uint32_t aaddr, uint32_t baddr, uint32_t b2addr) {
    #pragma unroll
    for (int k = 0; k < 12; k++) {
        uint32_t ah0[4], ah1[4], bh[4], b2[2];
        ldsm_x4(ah0, aaddr);
        ldsm_x4(ah1, aaddr + 16 * AP);
        ldsm_x4(bh, baddr);
        ldsm_x2(b2, b2addr);
        mma6(acc, ah0, ah1, bh, b2);
        uint32_t al0[4], al1[4];
        ldsm_x4(al0, aaddr + (AL_B - AH_B));
        ldsm_x4(al1, aaddr + (AL_B - AH_B) + 16 * AP);
        mma6(acc, al0, al1, bh, b2);
        aaddr += 32; baddr += 32; b2addr += 32;
    }
}

__device__ __forceinline__ void stage_chunk(uint32_t sb, int c, int tid) {
    const char* src = g_wblob + (size_t)c * 38400;
    #pragma unroll 1
    for (int i = tid; i < 2400; i += NTHREADS) {
        asm volatile("cp.async.cg.shared.global [%0], [%1], 16;"
                     :: "r"(sb + B_B + i * 16), "l"(src + (size_t)i * 16));
    }
    asm volatile("cp.async.commit_group;" ::: "memory");
}
#define CPWAIT() asm volatile("cp.async.wait_group 0;" ::: "memory")

__global__ void prep_weights(const float* __restrict__ qkv_w, const float* __restrict__ proj_w) {
    int idx = blockIdx.x * 256 + threadIdx.x;      // < 8*96*96 = 73728
    int c  = idx / 9216;
    int r  = idx - c * 9216;
    int j  = r / 96, kp = r - (r / 96) * 96;
    int grow = (c < 6) ? ((j >> 5) * 192 + c * 32 + (j & 31)) : ((c - 6) * 96 + j);
    const float2* src = (c < 6) ? (const float2*)qkv_w : (const float2*)proj_w;
    float2 v = src[(size_t)grow * 96 + kp];
    *(__half2*)(g_wblob + (size_t)c * 38400 + j * AP + kp * 4) =
        __floats2half2_rn(v.x, v.y);
}

__global__ void __launch_bounds__(NTHREADS, 1)
wmsa_hmma(const float* __restrict__ x,
          const float* __restrict__ qkv_b,
          const float* __restrict__ proj_b,
          const float* __restrict__ rpe_table,
          const int*   __restrict__ rpe_idx,
          float* __restrict__ out)
{
    extern __shared__ __align__(16) char smem[];
    float* sf = (float*)smem;
    const uint32_t sb = smem_u32(smem);
    const int tid  = threadIdx.x;
    const int warp = tid >> 5;
    const int lane = tid & 31;
    const int wm   = warp >> 2;
    const int wn   = warp & 3;
    const int bid  = blockIdx.x;     // 2 windows

    // ---- preload bias + rpe; zero q/k pad rows + vt image ----
    float* sbias = sf + SBIAS_F;
    for (int i = tid; i < 576; i += NTHREADS) sbias[i] = qkv_b[i];
    for (int i = tid; i < 192; i += NTHREADS) sbias[576 + i] = proj_b[i];
    uint8_t* rpi = (uint8_t*)(smem + RPI_B);
    float*   rpt = sf + RPT_F;
    for (int i = tid; i < 49 * 49; i += NTHREADS) rpi[i] = (uint8_t)rpe_idx[i];
    for (int i = tid; i < 169 * 6; i += NTHREADS) rpt[i] = rpe_table[i];
    {
        uint32_t* z1 = (uint32_t*)(smem + QI_B + 98 * 80);
        uint32_t* z2 = (uint32_t*)(smem + KI_B + 98 * 80);
        for (int i = tid; i < 440; i += NTHREADS) { z1[i] = 0u; z2[i] = 0u; }
        uint32_t* z3 = (uint32_t*)(smem + VTH_B);
        for (int i = tid; i < 2304; i += NTHREADS) z3[i] = 0u;
    }

    // ---- stage x -> fp16 hi/lo into A ----
    {
        const float2* xg = (const float2*)(x + (size_t)bid * 98 * 192);
        for (int idx = tid; idx < 98 * 96; idx += NTHREADS) {
            int r = idx / 96, kp = idx - (idx / 96) * 96;
            __half2 hi, lo;
            split16(xg[idx], hi, lo);
            *(__half2*)(smem + AH_B + r * AP + kp * 4) = hi;
            *(__half2*)(smem + AL_B + r * AP + kp * 4) = lo;
        }
    }
    stage_chunk(sb, 0, tid);

    // ---- GEMM ldmatrix addresses ----
    const uint32_t aaddr = sb + AH_B
        + (uint32_t)(wm * 32 + (lane & 7) + ((lane >> 3) & 1) * 8) * AP
        + (uint32_t)((lane >> 4) * 16);
    const uint32_t baddr = sb + B_B
        + (uint32_t)(wn * 24 + (lane & 7) + ((lane >> 4) & 1) * 8) * AP
        + (uint32_t)(((lane >> 3) & 1) * 16);
    const int l15 = lane & 15;
    const uint32_t b2addr = sb + B_B
        + (uint32_t)(wn * 24 + 16 + (l15 & 7)) * AP
        + (uint32_t)((l15 >> 3) * 16);

    // ---- attention warp geometry ----
    const int mt  = warp & 7;        // m16 tile: window*4 + tm
    const int win = mt >> 2;
    const int tm  = mt & 3;
    const int nh  = warp >> 3;       // dim half 0/1
    const int qr  = lane >> 2;       // quad row
    const int qc  = (lane & 3) * 2;  // quad col base
    const int iA  = tm * 16 + qr;    // local row within window (0..63)
    const int iB  = iA + 8;
    const int iAc = (iA < 49 ? iA : 48) * 49;
    const int iBc = (iB < 49 ? iB : 48) * 49;
    const uint32_t qaddr = sb + QI_B
        + (uint32_t)(win * 49 + tm * 16 + (lane & 7) + ((lane >> 3) & 1) * 8) * 80
        + (uint32_t)((lane >> 4) * 16);
    const uint32_t kaddr0 = sb + KI_B
        + (uint32_t)(win * 49 + (lane & 7) + (lane >> 4) * 8) * 80
        + (uint32_t)(((lane >> 3) & 1) * 16);
    const uint32_t vtaddr = sb + VTH_B + (uint32_t)(win * VT_WIN)
        + (uint32_t)(nh * 16 + (lane & 7) + (lane >> 4) * 8) * 144
        + (uint32_t)(((lane >> 3) & 1) * 16);

    char* aob = g_ao + (size_t)bid * 78400;

    // ================= Phase 1+2: per-head GEMM + HMMA attention =================
    for (int h = 0; h < 6; h++) {
        CPWAIT();
        __syncthreads();                 // B(h) staged; prior attention reads done

        float acc[24];
        #pragma unroll
        for (int i = 0; i < 24; i++) acc[i] = 0.f;
        run_gemm(acc, aaddr, baddr, b2addr);
        __syncthreads();                 // B(h) ldsm reads done

        stage_chunk(sb, h + 1, tid);     // prefetch next chunk under epilogue+attention

        // epilogue: q/k -> fp16 images (+bias, q scaled); v -> transposed fp16 (hi only)
        #pragma unroll
        for (int t = 0; t < 2; t++) {
            #pragma unroll
            for (int u = 0; u < 3; u++) {
                int r0e = wm * 32 + t * 16 + (lane >> 2);
                int c   = wn * 24 + u * 8 + (lane & 3) * 2;
                int blk = c >> 5, cc = c & 31;
                float bb0 = sbias[blk * 192 + h * 32 + cc];
                float bb1 = sbias[blk * 192 + h * 32 + cc + 1];
                const float* a = acc + t * 12 + u * 4;
                #pragma unroll
                for (int rr = 0; rr < 2; rr++) {
                    int r = r0e + rr * 8;
                    if (r < 98) {
                        float v0 = a[rr * 2 + 0] + bb0;
                        float v1 = a[rr * 2 + 1] + bb1;
                        if (blk == 0) {
                            *(__half2*)(smem + QI_B + r * 80 + cc * 2) =
                                __floats2half2_rn(v0 * SCALE, v1 * SCALE);
                        } else if (blk == 1) {
                            *(__half2*)(smem + KI_B + r * 80 + cc * 2) =
                                __floats2half2_rn(v0, v1);
                        } else {
                            int w2 = (r >= 49);
                            int key = r - w2 * 49;
                            char* vh = smem + VTH_B + w2 * VT_WIN + key * 2;
                            *(__half*)(vh + cc * 144)       = __float2half_rn(v0);
                            *(__half*)(vh + (cc + 1) * 144) = __float2half_rn(v1);
                        }
                    }
                }
            }
        }
        __syncthreads();                 // q/k/vt images ready

        // ---- S = Q K^T (fragments) ----
        float s[7][4];
        #pragma unroll
        for (int i = 0; i < 7; i++) { s[i][0] = s[i][1] = s[i][2] = s[i][3] = 0.f; }
        uint32_t a0[4], a1[4];
        ldsm_x4(a0, qaddr);
        ldsm_x4(a1, qaddr + 32);
        #pragma unroll
        for (int t16 = 0; t16 < 4; t16++) {
            uint32_t b0[4], b1[4];
            uint32_t ka = kaddr0 + (uint32_t)(t16 * 16) * 80;
            ldsm_x4(b0, ka);
            ldsm_x4(b1, ka + 32);
            mma_step(s[2 * t16], a0, b0 + 0);
            mma_step(s[2 * t16], a1, b1 + 0);
            if (t16 < 3) {
                mma_step(s[2 * t16 + 1], a0, b0 + 2);
                mma_step(s[2 * t16 + 1], a1, b1 + 2);
            }
        }

        // ---- bias + mask + softmax in fragments ----
        float mx0 = -1e30f, mx1 = -1e30f;
        #pragma unroll
        for (int t = 0; t < 7; t++) {
            int c0 = t * 8 + qc, c1 = c0 + 1;
            if (c0 < 49) { s[t][0] += rpt[rpi[iAc + c0] * 6 + h]; s[t][2] += rpt[rpi[iBc + c0] * 6 + h]; }
            else         { s[t][0] = -1e30f; s[t][2] = -1e30f; }
            if (c1 < 49) { s[t][1] += rpt[rpi[iAc + c1] * 6 + h]; s[t][3] += rpt[rpi[iBc + c1] * 6 + h]; }
            else         { s[t][1] = -1e30f; s[t][3] = -1e30f; }
            mx0 = fmaxf(mx0, fmaxf(s[t][0], s[t][1]));
            mx1 = fmaxf(mx1, fmaxf(s[t][2], s[t][3]));
        }
        mx0 = fmaxf(mx0, __shfl_xor_sync(0xffffffffu, mx0, 1));
        mx0 = fmaxf(mx0, __shfl_xor_sync(0xffffffffu, mx0, 2));
        mx1 = fmaxf(mx1, __shfl_xor_sync(0xffffffffu, mx1, 1));
        mx1 = fmaxf(mx1, __shfl_xor_sync(0xffffffffu, mx1, 2));
        float sm0 = 0.f, sm1 = 0.f;
        #pragma unroll
        for (int t = 0; t < 7; t++) {
            s[t][0] = __expf(s[t][0] - mx0); s[t][1] = __expf(s[t][1] - mx0);
            s[t][2] = __expf(s[t][2] - mx1); s[t][3] = __expf(s[t][3] - mx1);
            sm0 += s[t][0] + s[t][1];
            sm1 += s[t][2] + s[t][3];
        }
        sm0 += __shfl_xor_sync(0xffffffffu, sm0, 1);
        sm0 += __shfl_xor_sync(0xffffffffu, sm0, 2);
        sm1 += __shfl_xor_sync(0xffffffffu, sm1, 1);
        sm1 += __shfl_xor_sync(0xffffffffu, sm1, 2);
        float iv0 = 1.0f / sm0, iv1 = 1.0f / sm1;

        // ---- P fragments (hi/lo), accumulator layout == A-fragment layout ----
        uint32_t phi[4][4], plo[4][4];
        #pragma unroll
        for (int kc = 0; kc < 4; kc++) {
            #pragma unroll
            for (int h2i = 0; h2i < 4; h2i++) {
                int t = 2 * kc + (h2i >> 1);
                int rsel = (h2i & 1) * 2;
                float p0, p1;
                if (t < 7) {
                    float ivx = (h2i & 1) ? iv1 : iv0;
                    p0 = s[t][rsel + 0] * ivx;
                    p1 = s[t][rsel + 1] * ivx;
                } else { p0 = 0.f; p1 = 0.f; }
                __half hp0 = __float2half_rn(p0), hp1 = __float2half_rn(p1);
                phi[kc][h2i] = pack_h2(hp0, hp1);
                plo[kc][h2i] = pack_h2(__float2half_rn(p0 - __half2float(hp0)),
                                       __float2half_rn(p1 - __half2float(hp1)));
            }
        }

        // ---- PV: 2-pass (Phi + Plo) * Vhi ----
        float o0[4] = {0.f, 0.f, 0.f, 0.f};
        float o1[4] = {0.f, 0.f, 0.f, 0.f};
        #pragma unroll
        for (int kc = 0; kc < 4; kc++) {
            uint32_t vh[4];
            ldsm_x4(vh, vtaddr + (uint32_t)(kc * 32));
            mma_step(o0, phi[kc], vh + 0);
            mma_step(o1, phi[kc], vh + 2);
            mma_step(o0, plo[kc], vh + 0);
            mma_step(o1, plo[kc], vh + 2);
        }

        // ---- store ao rows as fp16 hi/lo in A-image layout ----
        {
            int dn = h * 32 + nh * 16 + qc;
            if (iA < 49) {
                int r = win * 49 + iA;
                __half2 hi, lo;
                split16(make_float2(o0[0], o0[1]), hi, lo);
                *(__half2*)(aob + r * AP + dn * 2)         = hi;
                *(__half2*)(aob + 39200 + r * AP + dn * 2) = lo;
                split16(make_float2(o1[0], o1[1]), hi, lo);
                *(__half2*)(aob + r * AP + dn * 2 + 16)         = hi;
                *(__half2*)(aob + 39200 + r * AP + dn * 2 + 16) = lo;
            }
            if (iB < 49) {
                int r = win * 49 + iB;
                __half2 hi, lo;
                split16(make_float2(o0[2], o0[3]), hi, lo);
                *(__half2*)(aob + r * AP + dn * 2)         = hi;
                *(__half2*)(aob + 39200 + r * AP + dn * 2) = lo;
                split16(make_float2(o1[2], o1[3]), hi, lo);
                *(__half2*)(aob + r * AP + dn * 2 + 16)         = hi;
                *(__half2*)(aob + 39200 + r * AP + dn * 2 + 16) = lo;
            }
        }
    }
    __syncthreads();   // all ao writes done (also fences global within CTA)

    // ---- stage A for phase 3: cp.async the pre-formatted ao blob ----
    {
        #pragma unroll 1
        for (int i = tid; i < 4900; i += NTHREADS) {
            asm volatile("cp.async.cg.shared.global [%0], [%1], 16;"
                         :: "r"(sb + AH_B + i * 16), "l"(aob + (size_t)i * 16));
        }
        asm volatile("cp.async.commit_group;" ::: "memory");
    }

    // ================= Phase 3: out = ao @ proj_w^T + b =================
    for (int s2 = 0; s2 < 2; s2++) {
        CPWAIT();
        __syncthreads();

        float acc[24];
        #pragma unroll
        for (int i = 0; i < 24; i++) acc[i] = 0.f;
        run_gemm(acc, aaddr, baddr, b2addr);
        __syncthreads();
        if (s2 == 0) stage_chunk(sb, 7, tid);

        #pragma unroll
        for (int t = 0; t < 2; t++) {
            #pragma unroll
            for (int u = 0; u < 3; u++) {
                int r0e = wm * 32 + t * 16 + (lane >> 2);
                int c   = wn * 24 + u * 8 + (lane & 3) * 2;
                int gcol = s2 * 96 + c;
                float bb0 = sbias[576 + gcol];
                float bb1 = sbias[576 + gcol + 1];
                const float* a = acc + t * 12 + u * 4;
                #pragma unroll
                for (int rr = 0; rr < 2; rr++) {
                    int r = r0e + rr * 8;
                    if (r < 98) {
                        float2 v = make_float2(a[rr * 2 + 0] + bb0, a[rr * 2 + 1] + bb1);
                        *(float2*)(out + ((size_t)bid * 98 + r) * 192 + gcol) = v;
                    }
                }
            }
        }
    }
}

extern "C" void kernel_launch(void* const* d_in, const int* in_sizes, int n_in,
                              void* d_out, int out_size)
{
    const float* x         = (const float*)d_in[0];
    const float* qkv_w     = (const float*)d_in[1];
    const float* qkv_b     = (const float*)d_in[2];
    const float* proj_w    = (const float*)d_in[3];
    const float* proj_b    = (const float*)d_in[4];
    const float* rpe_table = (const float*)d_in[5];
    const int*   rpe_idx   = (const int*)d_in[6];
    float* out = (float*)d_out;

    prep_weights<<<288, 256>>>(qkv_w, proj_w);

    cudaFuncSetAttribute(wmsa_hmma,
                         cudaFuncAttributeMaxDynamicSharedMemorySize, SMEM_TOTAL);
    wmsa_hmma<<<2048, NTHREADS, SMEM_TOTAL>>>(
        x, qkv_b, proj_b, rpe_table, rpe_idx, out);
}

// round 15
// speedup vs baseline: 5.4215x; 1.1865x over previous
#include <cuda_runtime.h>
#include <cuda_fp16.h>
#include <stdint.h>

#define NTHREADS 256
#define AP 400                    // A/B row pitch bytes (200 f16)
#define AH_B 0                    // 49 x 400
#define AL_B 19600                // 49 x 400
#define B_B  39200                // 96 x 400 (hi only)
#define QI_B 77600                // 64 rows x 80B
#define KI_B 82720                // 64 rows x 80B
#define VT_B 87840                // 32 dims x 144B
#define RPI_B 92448               // 2401 bytes
#define RPT_F 23713               // float idx (byte 94852), 1014 floats
#define SBIAS_F 24727             // float idx (byte 98908), 768 floats
#define SMEM_TOTAL 101984
#define SCALE 0.17677669529663687f

__device__ __align__(16) char g_ao[4096 * 39200];   // ao as fp16 hi|lo in A-image layout
__device__ __align__(16) char g_wblob[8 * 38400];   // pre-split fp16 hi weights

__device__ __forceinline__ uint32_t smem_u32(const void* p) {
    uint32_t a;
    asm("{ .reg .u64 t; cvta.to.shared.u64 t, %1; cvt.u32.u64 %0, t; }" : "=r"(a) : "l"(p));
    return a;
}
__device__ __forceinline__ uint32_t pack_h2(__half lo, __half hi) {
    return (uint32_t)__half_as_ushort(lo) | ((uint32_t)__half_as_ushort(hi) << 16);
}
__device__ __forceinline__ void ldsm_x4(uint32_t* r, uint32_t a) {
    asm volatile("ldmatrix.sync.aligned.m8n8.x4.shared.b16 {%0,%1,%2,%3}, [%4];"
                 : "=r"(r[0]), "=r"(r[1]), "=r"(r[2]), "=r"(r[3]) : "r"(a));
}
__device__ __forceinline__ void ldsm_x2(uint32_t* r, uint32_t a) {
    asm volatile("ldmatrix.sync.aligned.m8n8.x2.shared.b16 {%0,%1}, [%2];"
                 : "=r"(r[0]), "=r"(r[1]) : "r"(a));
}
__device__ __forceinline__ void mma_step(float* d, const uint32_t* a, const uint32_t* b) {
    asm volatile(
        "mma.sync.aligned.m16n8k16.row.col.f32.f16.f16.f32 "
        "{%0,%1,%2,%3}, {%4,%5,%6,%7}, {%8,%9}, {%0,%1,%2,%3};"
        : "+f"(d[0]), "+f"(d[1]), "+f"(d[2]), "+f"(d[3])
        : "r"(a[0]), "r"(a[1]), "r"(a[2]), "r"(a[3]), "r"(b[0]), "r"(b[1]));
}
__device__ __forceinline__ void mma6(float* acc, const uint32_t* a0, const uint32_t* a1,
                                     const uint32_t* b, const uint32_t* b2) {
    mma_step(acc + 0,  a0, b + 0);
    mma_step(acc + 4,  a0, b + 2);
    mma_step(acc + 8,  a0, b2);
    mma_step(acc + 12, a1, b + 0);
    mma_step(acc + 16, a1, b + 2);
    mma_step(acc + 20, a1, b2);
}
__device__ __forceinline__ void split16(float2 v, __half2& hi, __half2& lo) {
    __half hx = __float2half_rn(v.x), hy = __float2half_rn(v.y);
    hi = __halves2half2(hx, hy);
    lo = __halves2half2(__float2half_rn(v.x - __half2float(hx)),
                        __float2half_rn(v.y - __half2float(hy)));
}

// K=192 GEMM, 2 passes: (Ahi + Alo) * Bhi
__device__ __forceinline__ void run_gemm(float* acc, uint32_t aaddr, uint32_t baddr, uint32_t b2addr) {
    #pragma unroll
    for (int k = 0; k < 12; k++) {
        uint32_t ah0[4], ah1[4], bh[4], b2[2];
        ldsm_x4(ah0, aaddr);
        ldsm_x4(ah1, aaddr + 16 * AP);
        ldsm_x4(bh, baddr);
        ldsm_x2(b2, b2addr);
        mma6(acc, ah0, ah1, bh, b2);
        uint32_t al0[4], al1[4];
        ldsm_x4(al0, aaddr + (AL_B - AH_B));
        ldsm_x4(al1, aaddr + (AL_B - AH_B) + 16 * AP);
        mma6(acc, al0, al1, bh, b2);
        aaddr += 32; baddr += 32; b2addr += 32;
    }
}

__device__ __forceinline__ void stage_chunk(uint32_t sb, int c, int tid) {
    const char* src = g_wblob + (size_t)c * 38400;
    #pragma unroll 1
    for (int i = tid; i < 2400; i += NTHREADS) {
        asm volatile("cp.async.cg.shared.global [%0], [%1], 16;"
                     :: "r"(sb + B_B + i * 16), "l"(src + (size_t)i * 16));
    }
    asm volatile("cp.async.commit_group;" ::: "memory");
}
#define CPWAIT() asm volatile("cp.async.wait_group 0;" ::: "memory")

__global__ void prep_weights(const float* __restrict__ qkv_w, const float* __restrict__ proj_w) {
    int idx = blockIdx.x * 256 + threadIdx.x;      // < 8*96*96 = 73728
    int c  = idx / 9216;
    int r  = idx - c * 9216;
    int j  = r / 96, kp = r - (r / 96) * 96;
    int grow = (c < 6) ? ((j >> 5) * 192 + c * 32 + (j & 31)) : ((c - 6) * 96 + j);
    const float2* src = (c < 6) ? (const float2*)qkv_w : (const float2*)proj_w;
    float2 v = src[(size_t)grow * 96 + kp];
    *(__half2*)(g_wblob + (size_t)c * 38400 + j * AP + kp * 4) =
        __floats2half2_rn(v.x, v.y);
}

__global__ void __launch_bounds__(NTHREADS, 2)
wmsa_hmma(const float* __restrict__ x,
          const float* __restrict__ qkv_b,
          const float* __restrict__ proj_b,
          const float* __restrict__ rpe_table,
          const int*   __restrict__ rpe_idx,
          float* __restrict__ out)
{
    extern __shared__ __align__(16) char smem[];
    float* sf = (float*)smem;
    const uint32_t sb = smem_u32(smem);
    const int tid  = threadIdx.x;
    const int warp = tid >> 5;
    const int lane = tid & 31;
    const int wm   = warp >> 2;      // 0..1 (rows 32wm..32wm+31)
    const int wn   = warp & 3;       // 24-col slice
    const int bid  = blockIdx.x;     // 1 window

    // ---- preload bias + rpe; zero q/k pad rows + vt image ----
    float* sbias = sf + SBIAS_F;
    for (int i = tid; i < 576; i += NTHREADS) sbias[i] = qkv_b[i];
    for (int i = tid; i < 192; i += NTHREADS) sbias[576 + i] = proj_b[i];
    uint8_t* rpi = (uint8_t*)(smem + RPI_B);
    float*   rpt = sf + RPT_F;
    for (int i = tid; i < 49 * 49; i += NTHREADS) rpi[i] = (uint8_t)rpe_idx[i];
    for (int i = tid; i < 169 * 6; i += NTHREADS) rpt[i] = rpe_table[i];
    {
        uint32_t* z1 = (uint32_t*)(smem + QI_B + 49 * 80);
        uint32_t* z2 = (uint32_t*)(smem + KI_B + 49 * 80);
        for (int i = tid; i < 300; i += NTHREADS) { z1[i] = 0u; z2[i] = 0u; }
        uint32_t* z3 = (uint32_t*)(smem + VT_B);
        for (int i = tid; i < 1152; i += NTHREADS) z3[i] = 0u;
    }

    // ---- stage x -> fp16 hi/lo into A ----
    {
        const float2* xg = (const float2*)(x + (size_t)bid * 49 * 192);
        for (int idx = tid; idx < 49 * 96; idx += NTHREADS) {
            int r = idx / 96, kp = idx - (idx / 96) * 96;
            __half2 hi, lo;
            split16(xg[idx], hi, lo);
            *(__half2*)(smem + AH_B + r * AP + kp * 4) = hi;
            *(__half2*)(smem + AL_B + r * AP + kp * 4) = lo;
        }
    }
    stage_chunk(sb, 0, tid);

    // ---- GEMM ldmatrix addresses ----
    const uint32_t aaddr = sb + AH_B
        + (uint32_t)(wm * 32 + (lane & 7) + ((lane >> 3) & 1) * 8) * AP
        + (uint32_t)((lane >> 4) * 16);
    const uint32_t baddr = sb + B_B
        + (uint32_t)(wn * 24 + (lane & 7) + ((lane >> 4) & 1) * 8) * AP
        + (uint32_t)(((lane >> 3) & 1) * 16);
    const int l15 = lane & 15;
    const uint32_t b2addr = sb + B_B
        + (uint32_t)(wn * 24 + 16 + (l15 & 7)) * AP
        + (uint32_t)((l15 >> 3) * 16);

    // ---- attention warp geometry ----
    const int mt  = warp & 3;        // m16 tile (rows 16mt..16mt+15)
    const int nh  = warp >> 2;       // dim half 0/1
    const int qr  = lane >> 2;       // quad row
    const int qc  = (lane & 3) * 2;  // quad col base
    const int iA  = mt * 16 + qr;    // row within window (0..63)
    const int iB  = iA + 8;
    const int iAc = (iA < 49 ? iA : 48) * 49;
    const int iBc = (iB < 49 ? iB : 48) * 49;
    const uint32_t qaddr = sb + QI_B
        + (uint32_t)(mt * 16 + (lane & 7) + ((lane >> 3) & 1) * 8) * 80
        + (uint32_t)((lane >> 4) * 16);
    const uint32_t kaddr0 = sb + KI_B
        + (uint32_t)((lane & 7) + (lane >> 4) * 8) * 80
        + (uint32_t)(((lane >> 3) & 1) * 16);
    const uint32_t vtaddr = sb + VT_B
        + (uint32_t)(nh * 16 + (lane & 7) + (lane >> 4) * 8) * 144
        + (uint32_t)(((lane >> 3) & 1) * 16);

    char* aob = g_ao + (size_t)bid * 39200;

    // ================= Phase 1+2: per-head GEMM + HMMA attention =================
    for (int h = 0; h < 6; h++) {
        CPWAIT();
        __syncthreads();                 // B(h) staged; prior attention reads done

        float acc[24];
        #pragma unroll
        for (int i = 0; i < 24; i++) acc[i] = 0.f;
        run_gemm(acc, aaddr, baddr, b2addr);
        __syncthreads();                 // B(h) ldsm reads done

        stage_chunk(sb, h + 1, tid);     // prefetch next chunk under epilogue+attention

        // epilogue: q/k -> fp16 images (+bias, q scaled); v -> transposed fp16
        #pragma unroll
        for (int t = 0; t < 2; t++) {
            #pragma unroll
            for (int u = 0; u < 3; u++) {
                int r0e = wm * 32 + t * 16 + (lane >> 2);
                int c   = wn * 24 + u * 8 + (lane & 3) * 2;
                int blk = c >> 5, cc = c & 31;
                float bb0 = sbias[blk * 192 + h * 32 + cc];
                float bb1 = sbias[blk * 192 + h * 32 + cc + 1];
                const float* a = acc + t * 12 + u * 4;
                #pragma unroll
                for (int rr = 0; rr < 2; rr++) {
                    int r = r0e + rr * 8;
                    if (r < 49) {
                        float v0 = a[rr * 2 + 0] + bb0;
                        float v1 = a[rr * 2 + 1] + bb1;
                        if (blk == 0) {
                            *(__half2*)(smem + QI_B + r * 80 + cc * 2) =
                                __floats2half2_rn(v0 * SCALE, v1 * SCALE);
                        } else if (blk == 1) {
                            *(__half2*)(smem + KI_B + r * 80 + cc * 2) =
                                __floats2half2_rn(v0, v1);
                        } else {
                            char* vh = smem + VT_B + r * 2;
                            *(__half*)(vh + cc * 144)       = __float2half_rn(v0);
                            *(__half*)(vh + (cc + 1) * 144) = __float2half_rn(v1);
                        }
                    }
                }
            }
        }
        __syncthreads();                 // q/k/vt images ready

        // ---- S = Q K^T (fragments) ----
        float s[7][4];
        #pragma unroll
        for (int i = 0; i < 7; i++) { s[i][0] = s[i][1] = s[i][2] = s[i][3] = 0.f; }
        uint32_t a0[4], a1[4];
        ldsm_x4(a0, qaddr);
        ldsm_x4(a1, qaddr + 32);
        #pragma unroll
        for (int t16 = 0; t16 < 4; t16++) {
            uint32_t b0[4], b1[4];
            uint32_t ka = kaddr0 + (uint32_t)(t16 * 16) * 80;
            ldsm_x4(b0, ka);
            ldsm_x4(b1, ka + 32);
            mma_step(s[2 * t16], a0, b0 + 0);
            mma_step(s[2 * t16], a1, b1 + 0);
            if (t16 < 3) {
                mma_step(s[2 * t16 + 1], a0, b0 + 2);
                mma_step(s[2 * t16 + 1], a1, b1 + 2);
            }
        }

        // ---- bias + mask + softmax in fragments ----
        float mx0 = -1e30f, mx1 = -1e30f;
        #pragma unroll
        for (int t = 0; t < 7; t++) {
            int c0 = t * 8 + qc, c1 = c0 + 1;
            if (c0 < 49) { s[t][0] += rpt[rpi[iAc + c0] * 6 + h]; s[t][2] += rpt[rpi[iBc + c0] * 6 + h]; }
            else         { s[t][0] = -1e30f; s[t][2] = -1e30f; }
            if (c1 < 49) { s[t][1] += rpt[rpi[iAc + c1] * 6 + h]; s[t][3] += rpt[rpi[iBc + c1] * 6 + h]; }
            else         { s[t][1] = -1e30f; s[t][3] = -1e30f; }
            mx0 = fmaxf(mx0, fmaxf(s[t][0], s[t][1]));
            mx1 = fmaxf(mx1, fmaxf(s[t][2], s[t][3]));
        }
        mx0 = fmaxf(mx0, __shfl_xor_sync(0xffffffffu, mx0, 1));
        mx0 = fmaxf(mx0, __shfl_xor_sync(0xffffffffu, mx0, 2));
        mx1 = fmaxf(mx1, __shfl_xor_sync(0xffffffffu, mx1, 1));
        mx1 = fmaxf(mx1, __shfl_xor_sync(0xffffffffu, mx1, 2));
        float sm0 = 0.f, sm1 = 0.f;
        #pragma unroll
        for (int t = 0; t < 7; t++) {
            s[t][0] = __expf(s[t][0] - mx0); s[t][1] = __expf(s[t][1] - mx0);
            s[t][2] = __expf(s[t][2] - mx1); s[t][3] = __expf(s[t][3] - mx1);
            sm0 += s[t][0] + s[t][1];
            sm1 += s[t][2] + s[t][3];
        }
        sm0 += __shfl_xor_sync(0xffffffffu, sm0, 1);
        sm0 += __shfl_xor_sync(0xffffffffu, sm0, 2);
        sm1 += __shfl_xor_sync(0xffffffffu, sm1, 1);
        sm1 += __shfl_xor_sync(0xffffffffu, sm1, 2);
        float iv0 = 1.0f / sm0, iv1 = 1.0f / sm1;

        // ---- P fragments (hi/lo), accumulator layout == A-fragment layout ----
        uint32_t phi[4][4], plo[4][4];
        #pragma unroll
        for (int kc = 0; kc < 4; kc++) {
            #pragma unroll
            for (int h2i = 0; h2i < 4; h2i++) {
                int t = 2 * kc + (h2i >> 1);
                int rsel = (h2i & 1) * 2;
                float p0, p1;
                if (t < 7) {
                    float ivx = (h2i & 1) ? iv1 : iv0;
                    p0 = s[t][rsel + 0] * ivx;
                    p1 = s[t][rsel + 1] * ivx;
                } else { p0 = 0.f; p1 = 0.f; }
                __half hp0 = __float2half_rn(p0), hp1 = __float2half_rn(p1);
                phi[kc][h2i] = pack_h2(hp0, hp1);
                plo[kc][h2i] = pack_h2(__float2half_rn(p0 - __half2float(hp0)),
                                       __float2half_rn(p1 - __half2float(hp1)));
            }
        }

        // ---- PV: 2-pass (Phi + Plo) * Vhi ----
        float o0[4] = {0.f, 0.f, 0.f, 0.f};
        float o1[4] = {0.f, 0.f, 0.f, 0.f};
        #pragma unroll
        for (int kc = 0; kc < 4; kc++) {
            uint32_t vh[4];
            ldsm_x4(vh, vtaddr + (uint32_t)(kc * 32));
            mma_step(o0, phi[kc], vh + 0);
            mma_step(o1, phi[kc], vh + 2);
            mma_step(o0, plo[kc], vh + 0);
            mma_step(o1, plo[kc], vh + 2);
        }

        // ---- store ao rows as fp16 hi/lo in A-image layout ----
        {
            int dn = h * 32 + nh * 16 + qc;
            if (iA < 49) {
                __half2 hi, lo;
                split16(make_float2(o0[0], o0[1]), hi, lo);
                *(__half2*)(aob + iA * AP + dn * 2)         = hi;
                *(__half2*)(aob + 19600 + iA * AP + dn * 2) = lo;
                split16(make_float2(o1[0], o1[1]), hi, lo);
                *(__half2*)(aob + iA * AP + dn * 2 + 16)         = hi;
                *(__half2*)(aob + 19600 + iA * AP + dn * 2 + 16) = lo;
            }
            if (iB < 49) {
                __half2 hi, lo;
                split16(make_float2(o0[2], o0[3]), hi, lo);
                *(__half2*)(aob + iB * AP + dn * 2)         = hi;
                *(__half2*)(aob + 19600 + iB * AP + dn * 2) = lo;
                split16(make_float2(o1[2], o1[3]), hi, lo);
                *(__half2*)(aob + iB * AP + dn * 2 + 16)         = hi;
                *(__half2*)(aob + 19600 + iB * AP + dn * 2 + 16) = lo;
            }
        }
    }
    __syncthreads();   // all ao writes done

    // ---- stage A for phase 3: cp.async the pre-formatted ao blob ----
    {
        #pragma unroll 1
        for (int i = tid; i < 2450; i += NTHREADS) {
            asm volatile("cp.async.cg.shared.global [%0], [%1], 16;"
                         :: "r"(sb + AH_B + i * 16), "l"(aob + (size_t)i * 16));
        }
        asm volatile("cp.async.commit_group;" ::: "memory");
    }

    // ================= Phase 3: out = ao @ proj_w^T + b =================
    for (int s2 = 0; s2 < 2; s2++) {
        CPWAIT();
        __syncthreads();

        float acc[24];
        #pragma unroll
        for (int i = 0; i < 24; i++) acc[i] = 0.f;
        run_gemm(acc, aaddr, baddr, b2addr);
        __syncthreads();
        if (s2 == 0) stage_chunk(sb, 7, tid);

        #pragma unroll
        for (int t = 0; t < 2; t++) {
            #pragma unroll
            for (int u = 0; u < 3; u++) {
                int r0e = wm * 32 + t * 16 + (lane >> 2);
                int c   = wn * 24 + u * 8 + (lane & 3) * 2;
                int gcol = s2 * 96 + c;
                float bb0 = sbias[576 + gcol];
                float bb1 = sbias[576 + gcol + 1];
                const float* a = acc + t * 12 + u * 4;
                #pragma unroll
                for (int rr = 0; rr < 2; rr++) {
                    int r = r0e + rr * 8;
                    if (r < 49) {
                        float2 v = make_float2(a[rr * 2 + 0] + bb0, a[rr * 2 + 1] + bb1);
                        *(float2*)(out + ((size_t)bid * 49 + r) * 192 + gcol) = v;
                    }
                }
            }
        }
    }
}

extern "C" void kernel_launch(void* const* d_in, const int* in_sizes, int n_in,
                              void* d_out, int out_size)
{
    const float* x         = (const float*)d_in[0];
    const float* qkv_w     = (const float*)d_in[1];
    const float* qkv_b     = (const float*)d_in[2];
    const float* proj_w    = (const float*)d_in[3];
    const float* proj_b    = (const float*)d_in[4];
    const float* rpe_table = (const float*)d_in[5];
    const int*   rpe_idx   = (const int*)d_in[6];
    float* out = (float*)d_out;

    prep_weights<<<288, 256>>>(qkv_w, proj_w);

    cudaFuncSetAttribute(wmsa_hmma,
                         cudaFuncAttributeMaxDynamicSharedMemorySize, SMEM_TOTAL);
    wmsa_hmma<<<4096, NTHREADS, SMEM_TOTAL>>>(
        x, qkv_b, proj_b, rpe_table, rpe_idx, out);
}

// round 16
// speedup vs baseline: 5.9578x; 1.0989x over previous
#include <cuda_runtime.h>
#include <cuda_fp16.h>
#include <stdint.h>

#define NTHREADS 256
#define AP 400                    // A/B row pitch bytes (200 f16)
#define AH_B 0                    // 49 x 400
#define AL_B 19600                // 49 x 400 (phase-3 ao-lo only)
#define B_B  39200                // 96 x 400 (hi only)
#define QI_B 77600                // 64 rows x 80B
#define KI_B 82720                // 64 rows x 80B
#define VT_B 87840                // 32 dims x 144B
#define RPI_B 92448               // 2401 bytes
#define RPT_F 23713               // float idx (byte 94852), 1014 floats
#define SBIAS_F 24727             // float idx (byte 98908), 768 floats
#define SMEM_TOTAL 101984
#define SCALE 0.17677669529663687f

__device__ __align__(16) char g_ao[4096 * 39200];   // ao as fp16 hi|lo in A-image layout
__device__ __align__(16) char g_wblob[8 * 38400];   // pre-split fp16 hi weights

__device__ __forceinline__ uint32_t smem_u32(const void* p) {
    uint32_t a;
    asm("{ .reg .u64 t; cvta.to.shared.u64 t, %1; cvt.u32.u64 %0, t; }" : "=r"(a) : "l"(p));
    return a;
}
__device__ __forceinline__ uint32_t pack_h2(__half lo, __half hi) {
    return (uint32_t)__half_as_ushort(lo) | ((uint32_t)__half_as_ushort(hi) << 16);
}
__device__ __forceinline__ void ldsm_x4(uint32_t* r, uint32_t a) {
    asm volatile("ldmatrix.sync.aligned.m8n8.x4.shared.b16 {%0,%1,%2,%3}, [%4];"
                 : "=r"(r[0]), "=r"(r[1]), "=r"(r[2]), "=r"(r[3]) : "r"(a));
}
__device__ __forceinline__ void ldsm_x2(uint32_t* r, uint32_t a) {
    asm volatile("ldmatrix.sync.aligned.m8n8.x2.shared.b16 {%0,%1}, [%2];"
                 : "=r"(r[0]), "=r"(r[1]) : "r"(a));
}
__device__ __forceinline__ void mma_step(float* d, const uint32_t* a, const uint32_t* b) {
    asm volatile(
        "mma.sync.aligned.m16n8k16.row.col.f32.f16.f16.f32 "
        "{%0,%1,%2,%3}, {%4,%5,%6,%7}, {%8,%9}, {%0,%1,%2,%3};"
        : "+f"(d[0]), "+f"(d[1]), "+f"(d[2]), "+f"(d[3])
        : "r"(a[0]), "r"(a[1]), "r"(a[2]), "r"(a[3]), "r"(b[0]), "r"(b[1]));
}
__device__ __forceinline__ void mma6(float* acc, const uint32_t* a0, const uint32_t* a1,
                                     const uint32_t* b, const uint32_t* b2) {
    mma_step(acc + 0,  a0, b + 0);
    mma_step(acc + 4,  a0, b + 2);
    mma_step(acc + 8,  a0, b2);
    mma_step(acc + 12, a1, b + 0);
    mma_step(acc + 16, a1, b + 2);
    mma_step(acc + 20, a1, b2);
}
__device__ __forceinline__ void split16(float2 v, __half2& hi, __half2& lo) {
    __half hx = __float2half_rn(v.x), hy = __float2half_rn(v.y);
    hi = __halves2half2(hx, hy);
    lo = __halves2half2(__float2half_rn(v.x - __half2float(hx)),
                        __float2half_rn(v.y - __half2float(hy)));
}

// K=192 GEMM, single pass: Ahi * Bhi  (phase-1: attention re-rounds q/k anyway)
__device__ __forceinline__ void run_gemm1(float* acc, uint32_t aaddr, uint32_t baddr, uint32_t b2addr) {
    #pragma unroll
    for (int k = 0; k < 12; k++) {
        uint32_t ah0[4], ah1[4], bh[4], b2[2];
        ldsm_x4(ah0, aaddr);
        ldsm_x4(ah1, aaddr + 16 * AP);
        ldsm_x4(bh, baddr);
        ldsm_x2(b2, b2addr);
        mma6(acc, ah0, ah1, bh, b2);
        aaddr += 32; baddr += 32; b2addr += 32;
    }
}

// K=192 GEMM, 2 passes: (Ahi + Alo) * Bhi  (phase-3: direct path to output)
__device__ __forceinline__ void run_gemm2(float* acc, uint32_t aaddr, uint32_t baddr, uint32_t b2addr) {
    #pragma unroll
    for (int k = 0; k < 12; k++) {
        uint32_t ah0[4], ah1[4], bh[4], b2[2];
        ldsm_x4(ah0, aaddr);
        ldsm_x4(ah1, aaddr + 16 * AP);
        ldsm_x4(bh, baddr);
        ldsm_x2(b2, b2addr);
        mma6(acc, ah0, ah1, bh, b2);
        uint32_t al0[4], al1[4];
        ldsm_x4(al0, aaddr + (AL_B - AH_B));
        ldsm_x4(al1, aaddr + (AL_B - AH_B) + 16 * AP);
        mma6(acc, al0, al1, bh, b2);
        aaddr += 32; baddr += 32; b2addr += 32;
    }
}

__device__ __forceinline__ void stage_chunk(uint32_t sb, int c, int tid) {
    const char* src = g_wblob + (size_t)c * 38400;
    #pragma unroll 1
    for (int i = tid; i < 2400; i += NTHREADS) {
        asm volatile("cp.async.cg.shared.global [%0], [%1], 16;"
                     :: "r"(sb + B_B + i * 16), "l"(src + (size_t)i * 16));
    }
    asm volatile("cp.async.commit_group;" ::: "memory");
}
#define CPWAIT() asm volatile("cp.async.wait_group 0;" ::: "memory")

__global__ void prep_weights(const float* __restrict__ qkv_w, const float* __restrict__ proj_w) {
    int idx = blockIdx.x * 256 + threadIdx.x;      // < 8*96*96 = 73728
    int c  = idx / 9216;
    int r  = idx - c * 9216;
    int j  = r / 96, kp = r - (r / 96) * 96;
    int grow = (c < 6) ? ((j >> 5) * 192 + c * 32 + (j & 31)) : ((c - 6) * 96 + j);
    const float2* src = (c < 6) ? (const float2*)qkv_w : (const float2*)proj_w;
    float2 v = src[(size_t)grow * 96 + kp];
    *(__half2*)(g_wblob + (size_t)c * 38400 + j * AP + kp * 4) =
        __floats2half2_rn(v.x, v.y);
}

__global__ void __launch_bounds__(NTHREADS, 2)
wmsa_hmma(const float* __restrict__ x,
          const float* __restrict__ qkv_b,
          const float* __restrict__ proj_b,
          const float* __restrict__ rpe_table,
          const int*   __restrict__ rpe_idx,
          float* __restrict__ out)
{
    extern __shared__ __align__(16) char smem[];
    float* sf = (float*)smem;
    const uint32_t sb = smem_u32(smem);
    const int tid  = threadIdx.x;
    const int warp = tid >> 5;
    const int lane = tid & 31;
    const int wm   = warp >> 2;      // 0..1 (rows 32wm..32wm+31)
    const int wn   = warp & 3;       // 24-col slice
    const int bid  = blockIdx.x;     // 1 window

    // ---- preload bias + rpe; zero q/k pad rows + vt image ----
    float* sbias = sf + SBIAS_F;
    for (int i = tid; i < 576; i += NTHREADS) sbias[i] = qkv_b[i];
    for (int i = tid; i < 192; i += NTHREADS) sbias[576 + i] = proj_b[i];
    uint8_t* rpi = (uint8_t*)(smem + RPI_B);
    float*   rpt = sf + RPT_F;
    for (int i = tid; i < 49 * 49; i += NTHREADS) rpi[i] = (uint8_t)rpe_idx[i];
    for (int i = tid; i < 169 * 6; i += NTHREADS) rpt[i] = rpe_table[i];
    {
        uint32_t* z1 = (uint32_t*)(smem + QI_B + 49 * 80);
        uint32_t* z2 = (uint32_t*)(smem + KI_B + 49 * 80);
        for (int i = tid; i < 300; i += NTHREADS) { z1[i] = 0u; z2[i] = 0u; }
        uint32_t* z3 = (uint32_t*)(smem + VT_B);
        for (int i = tid; i < 1152; i += NTHREADS) z3[i] = 0u;
    }

    // ---- stage x -> fp16 hi into A (single-pass phase 1 needs no lo) ----
    {
        const float2* xg = (const float2*)(x + (size_t)bid * 49 * 192);
        for (int idx = tid; idx < 49 * 96; idx += NTHREADS) {
            int r = idx / 96, kp = idx - (idx / 96) * 96;
            float2 v = xg[idx];
            *(__half2*)(smem + AH_B + r * AP + kp * 4) = __floats2half2_rn(v.x, v.y);
        }
    }
    stage_chunk(sb, 0, tid);

    // ---- GEMM ldmatrix addresses ----
    const uint32_t aaddr = sb + AH_B
        + (uint32_t)(wm * 32 + (lane & 7) + ((lane >> 3) & 1) * 8) * AP
        + (uint32_t)((lane >> 4) * 16);
    const uint32_t baddr = sb + B_B
        + (uint32_t)(wn * 24 + (lane & 7) + ((lane >> 4) & 1) * 8) * AP
        + (uint32_t)(((lane >> 3) & 1) * 16);
    const int l15 = lane & 15;
    const uint32_t b2addr = sb + B_B
        + (uint32_t)(wn * 24 + 16 + (l15 & 7)) * AP
        + (uint32_t)((l15 >> 3) * 16);

    // ---- attention warp geometry ----
    const int mt  = warp & 3;        // m16 tile (rows 16mt..16mt+15)
    const int nh  = warp >> 2;       // dim half 0/1
    const int qr  = lane >> 2;       // quad row
    const int qc  = (lane & 3) * 2;  // quad col base
    const int iA  = mt * 16 + qr;    // row within window (0..63)
    const int iB  = iA + 8;
    const int iAc = (iA < 49 ? iA : 48) * 49;
    const int iBc = (iB < 49 ? iB : 48) * 49;
    const uint32_t qaddr = sb + QI_B
        + (uint32_t)(mt * 16 + (lane & 7) + ((lane >> 3) & 1) * 8) * 80
        + (uint32_t)((lane >> 4) * 16);
    const uint32_t kaddr0 = sb + KI_B
        + (uint32_t)((lane & 7) + (lane >> 4) * 8) * 80
        + (uint32_t)(((lane >> 3) & 1) * 16);
    const uint32_t vtaddr = sb + VT_B
        + (uint32_t)(nh * 16 + (lane & 7) + (lane >> 4) * 8) * 144
        + (uint32_t)(((lane >> 3) & 1) * 16);

    char* aob = g_ao + (size_t)bid * 39200;

    // ================= Phase 1+2: per-head GEMM + HMMA attention =================
    for (int h = 0; h < 6; h++) {
        CPWAIT();
        __syncthreads();                 // B(h) staged; prior attention reads done

        float acc[24];
        #pragma unroll
        for (int i = 0; i < 24; i++) acc[i] = 0.f;
        run_gemm1(acc, aaddr, baddr, b2addr);
        __syncthreads();                 // B(h) ldsm reads done

        stage_chunk(sb, h + 1, tid);     // prefetch next chunk under epilogue+attention

        // epilogue: q/k -> fp16 images (+bias, q scaled); v -> transposed fp16
        #pragma unroll
        for (int t = 0; t < 2; t++) {
            #pragma unroll
            for (int u = 0; u < 3; u++) {
                int r0e = wm * 32 + t * 16 + (lane >> 2);
                int c   = wn * 24 + u * 8 + (lane & 3) * 2;
                int blk = c >> 5, cc = c & 31;
                float bb0 = sbias[blk * 192 + h * 32 + cc];
                float bb1 = sbias[blk * 192 + h * 32 + cc + 1];
                const float* a = acc + t * 12 + u * 4;
                #pragma unroll
                for (int rr = 0; rr < 2; rr++) {
                    int r = r0e + rr * 8;
                    if (r < 49) {
                        float v0 = a[rr * 2 + 0] + bb0;
                        float v1 = a[rr * 2 + 1] + bb1;
                        if (blk == 0) {
                            *(__half2*)(smem + QI_B + r * 80 + cc * 2) =
                                __floats2half2_rn(v0 * SCALE, v1 * SCALE);
                        } else if (blk == 1) {
                            *(__half2*)(smem + KI_B + r * 80 + cc * 2) =
                                __floats2half2_rn(v0, v1);
                        } else {
                            char* vh = smem + VT_B + r * 2;
                            *(__half*)(vh + cc * 144)       = __float2half_rn(v0);
                            *(__half*)(vh + (cc + 1) * 144) = __float2half_rn(v1);
                        }
                    }
                }
            }
        }
        __syncthreads();                 // q/k/vt images ready

        // ---- S = Q K^T (fragments) ----
        float s[7][4];
        #pragma unroll
        for (int i = 0; i < 7; i++) { s[i][0] = s[i][1] = s[i][2] = s[i][3] = 0.f; }
        uint32_t a0[4], a1[4];
        ldsm_x4(a0, qaddr);
        ldsm_x4(a1, qaddr + 32);
        #pragma unroll
        for (int t16 = 0; t16 < 4; t16++) {
            uint32_t b0[4], b1[4];
            uint32_t ka = kaddr0 + (uint32_t)(t16 * 16) * 80;
            ldsm_x4(b0, ka);
            ldsm_x4(b1, ka + 32);
            mma_step(s[2 * t16], a0, b0 + 0);
            mma_step(s[2 * t16], a1, b1 + 0);
            if (t16 < 3) {
                mma_step(s[2 * t16 + 1], a0, b0 + 2);
                mma_step(s[2 * t16 + 1], a1, b1 + 2);
            }
        }

        // ---- bias + mask + softmax in fragments ----
        float mx0 = -1e30f, mx1 = -1e30f;
        #pragma unroll
        for (int t = 0; t < 7; t++) {
            int c0 = t * 8 + qc, c1 = c0 + 1;
            if (c0 < 49) { s[t][0] += rpt[rpi[iAc + c0] * 6 + h]; s[t][2] += rpt[rpi[iBc + c0] * 6 + h]; }
            else         { s[t][0] = -1e30f; s[t][2] = -1e30f; }
            if (c1 < 49) { s[t][1] += rpt[rpi[iAc + c1] * 6 + h]; s[t][3] += rpt[rpi[iBc + c1] * 6 + h]; }
            else         { s[t][1] = -1e30f; s[t][3] = -1e30f; }
            mx0 = fmaxf(mx0, fmaxf(s[t][0], s[t][1]));
            mx1 = fmaxf(mx1, fmaxf(s[t][2], s[t][3]));
        }
        mx0 = fmaxf(mx0, __shfl_xor_sync(0xffffffffu, mx0, 1));
        mx0 = fmaxf(mx0, __shfl_xor_sync(0xffffffffu, mx0, 2));
        mx1 = fmaxf(mx1, __shfl_xor_sync(0xffffffffu, mx1, 1));
        mx1 = fmaxf(mx1, __shfl_xor_sync(0xffffffffu, mx1, 2));
        float sm0 = 0.f, sm1 = 0.f;
        #pragma unroll
        for (int t = 0; t < 7; t++) {
            s[t][0] = __expf(s[t][0] - mx0); s[t][1] = __expf(s[t][1] - mx0);
            s[t][2] = __expf(s[t][2] - mx1); s[t][3] = __expf(s[t][3] - mx1);
            sm0 += s[t][0] + s[t][1];
            sm1 += s[t][2] + s[t][3];
        }
        sm0 += __shfl_xor_sync(0xffffffffu, sm0, 1);
        sm0 += __shfl_xor_sync(0xffffffffu, sm0, 2);
        sm1 += __shfl_xor_sync(0xffffffffu, sm1, 1);
        sm1 += __shfl_xor_sync(0xffffffffu, sm1, 2);
        float iv0 = 1.0f / sm0, iv1 = 1.0f / sm1;

        // ---- P fragments (hi/lo), accumulator layout == A-fragment layout ----
        uint32_t phi[4][4], plo[4][4];
        #pragma unroll
        for (int kc = 0; kc < 4; kc++) {
            #pragma unroll
            for (int h2i = 0; h2i < 4; h2i++) {
                int t = 2 * kc + (h2i >> 1);
                int rsel = (h2i & 1) * 2;
                float p0, p1;
                if (t < 7) {
                    float ivx = (h2i & 1) ? iv1 : iv0;
                    p0 = s[t][rsel + 0] * ivx;
                    p1 = s[t][rsel + 1] * ivx;
                } else { p0 = 0.f; p1 = 0.f; }
                __half hp0 = __float2half_rn(p0), hp1 = __float2half_rn(p1);
                phi[kc][h2i] = pack_h2(hp0, hp1);
                plo[kc][h2i] = pack_h2(__float2half_rn(p0 - __half2float(hp0)),
                                       __float2half_rn(p1 - __half2float(hp1)));
            }
        }

        // ---- PV: 2-pass (Phi + Plo) * Vhi ----
        float o0[4] = {0.f, 0.f, 0.f, 0.f};
        float o1[4] = {0.f, 0.f, 0.f, 0.f};
        #pragma unroll
        for (int kc = 0; kc < 4; kc++) {
            uint32_t vh[4];
            ldsm_x4(vh, vtaddr + (uint32_t)(kc * 32));
            mma_step(o0, phi[kc], vh + 0);
            mma_step(o1, phi[kc], vh + 2);
            mma_step(o0, plo[kc], vh + 0);
            mma_step(o1, plo[kc], vh + 2);
        }

        // ---- store ao rows as fp16 hi/lo in A-image layout ----
        {
            int dn = h * 32 + nh * 16 + qc;
            if (iA < 49) {
                __half2 hi, lo;
                split16(make_float2(o0[0], o0[1]), hi, lo);
                *(__half2*)(aob + iA * AP + dn * 2)         = hi;
                *(__half2*)(aob + 19600 + iA * AP + dn * 2) = lo;
                split16(make_float2(o1[0], o1[1]), hi, lo);
                *(__half2*)(aob + iA * AP + dn * 2 + 16)         = hi;
                *(__half2*)(aob + 19600 + iA * AP + dn * 2 + 16) = lo;
            }
            if (iB < 49) {
                __half2 hi, lo;
                split16(make_float2(o0[2], o0[3]), hi, lo);
                *(__half2*)(aob + iB * AP + dn * 2)         = hi;
                *(__half2*)(aob + 19600 + iB * AP + dn * 2) = lo;
                split16(make_float2(o1[2], o1[3]), hi, lo);
                *(__half2*)(aob + iB * AP + dn * 2 + 16)         = hi;
                *(__half2*)(aob + 19600 + iB * AP + dn * 2 + 16) = lo;
            }
        }
    }
    __syncthreads();   // all ao writes done

    // ---- stage A (hi+lo) for phase 3: cp.async the pre-formatted ao blob ----
    {
        #pragma unroll 1
        for (int i = tid; i < 2450; i += NTHREADS) {
            asm volatile("cp.async.cg.shared.global [%0], [%1], 16;"
                         :: "r"(sb + AH_B + i * 16), "l"(aob + (size_t)i * 16));
        }
        asm volatile("cp.async.commit_group;" ::: "memory");
    }

    // ================= Phase 3: out = ao @ proj_w^T + b (2-pass) =================
    for (int s2 = 0; s2 < 2; s2++) {
        CPWAIT();
        __syncthreads();

        float acc[24];
        #pragma unroll
        for (int i = 0; i < 24; i++) acc[i] = 0.f;
        run_gemm2(acc, aaddr, baddr, b2addr);
        __syncthreads();
        if (s2 == 0) stage_chunk(sb, 7, tid);

        #pragma unroll
        for (int t = 0; t < 2; t++) {
            #pragma unroll
            for (int u = 0; u < 3; u++) {
                int r0e = wm * 32 + t * 16 + (lane >> 2);
                int c   = wn * 24 + u * 8 + (lane & 3) * 2;
                int gcol = s2 * 96 + c;
                float bb0 = sbias[576 + gcol];
                float bb1 = sbias[576 + gcol + 1];
                const float* a = acc + t * 12 + u * 4;
                #pragma unroll
                for (int rr = 0; rr < 2; rr++) {
                    int r = r0e + rr * 8;
                    if (r < 49) {
                        float2 v = make_float2(a[rr * 2 + 0] + bb0, a[rr * 2 + 1] + bb1);
                        *(float2*)(out + ((size_t)bid * 49 + r) * 192 + gcol) = v;
                    }
                }
            }
        }
    }
}

extern "C" void kernel_launch(void* const* d_in, const int* in_sizes, int n_in,
                              void* d_out, int out_size)
{
    const float* x         = (const float*)d_in[0];
    const float* qkv_w     = (const float*)d_in[1];
    const float* qkv_b     = (const float*)d_in[2];
    const float* proj_w    = (const float*)d_in[3];
    const float* proj_b    = (const float*)d_in[4];
    const float* rpe_table = (const float*)d_in[5];
    const int*   rpe_idx   = (const int*)d_in[6];
    float* out = (float*)d_out;

    prep_weights<<<288, 256>>>(qkv_w, proj_w);

    cudaFuncSetAttribute(wmsa_hmma,
                         cudaFuncAttributeMaxDynamicSharedMemorySize, SMEM_TOTAL);
    wmsa_hmma<<<4096, NTHREADS, SMEM_TOTAL>>>(
        x, qkv_b, proj_b, rpe_table, rpe_idx, out);
}

// round 17
// speedup vs baseline: 6.5449x; 1.0986x over previous
#include <cuda_runtime.h>
#include <cuda_fp16.h>
#include <stdint.h>

#define NTHREADS 256
#define AP 400                    // A/B row pitch bytes (200 f16)
#define AH_B 0                    // 49 x 400 = 19600
#define B_B  19600                // 96 x 400 = 38400 -> 58000
#define QI_B 58000                // 64 rows x 80B
#define KI_B 63120
#define VI_B 68240                // V row-major [key][dim], 64 x 80B
#define RPI_B 73360               // 2401 bytes
#define RPT_F 18941               // float idx (byte 75764), 1014 floats
#define SBIAS_F 19955             // float idx (byte 79820), 768 floats
#define SMEM_TOTAL 82944
#define SCALE 0.17677669529663687f

__device__ __align__(16) char g_ao[4096 * 19600];   // ao as fp16 hi in A-image layout
__device__ __align__(16) char g_wblob[8 * 38400];   // pre-split fp16 hi weights

__device__ __forceinline__ uint32_t smem_u32(const void* p) {
    uint32_t a;
    asm("{ .reg .u64 t; cvta.to.shared.u64 t, %1; cvt.u32.u64 %0, t; }" : "=r"(a) : "l"(p));
    return a;
}
__device__ __forceinline__ uint32_t pack_h2(__half lo, __half hi) {
    return (uint32_t)__half_as_ushort(lo) | ((uint32_t)__half_as_ushort(hi) << 16);
}
__device__ __forceinline__ void ldsm_x4(uint32_t* r, uint32_t a) {
    asm volatile("ldmatrix.sync.aligned.m8n8.x4.shared.b16 {%0,%1,%2,%3}, [%4];"
                 : "=r"(r[0]), "=r"(r[1]), "=r"(r[2]), "=r"(r[3]) : "r"(a));
}
__device__ __forceinline__ void ldsm_x4_trans(uint32_t* r, uint32_t a) {
    asm volatile("ldmatrix.sync.aligned.m8n8.x4.trans.shared.b16 {%0,%1,%2,%3}, [%4];"
                 : "=r"(r[0]), "=r"(r[1]), "=r"(r[2]), "=r"(r[3]) : "r"(a));
}
__device__ __forceinline__ void ldsm_x2(uint32_t* r, uint32_t a) {
    asm volatile("ldmatrix.sync.aligned.m8n8.x2.shared.b16 {%0,%1}, [%2];"
                 : "=r"(r[0]), "=r"(r[1]) : "r"(a));
}
__device__ __forceinline__ void mma_step(float* d, const uint32_t* a, const uint32_t* b) {
    asm volatile(
        "mma.sync.aligned.m16n8k16.row.col.f32.f16.f16.f32 "
        "{%0,%1,%2,%3}, {%4,%5,%6,%7}, {%8,%9}, {%0,%1,%2,%3};"
        : "+f"(d[0]), "+f"(d[1]), "+f"(d[2]), "+f"(d[3])
        : "r"(a[0]), "r"(a[1]), "r"(a[2]), "r"(a[3]), "r"(b[0]), "r"(b[1]));
}
__device__ __forceinline__ void mma6(float* acc, const uint32_t* a0, const uint32_t* a1,
                                     const uint32_t* b, const uint32_t* b2) {
    mma_step(acc + 0,  a0, b + 0);
    mma_step(acc + 4,  a0, b + 2);
    mma_step(acc + 8,  a0, b2);
    mma_step(acc + 12, a1, b + 0);
    mma_step(acc + 16, a1, b + 2);
    mma_step(acc + 20, a1, b2);
}

// K=192 GEMM, single pass: Ahi * Bhi
__device__ __forceinline__ void run_gemm1(float* acc, uint32_t aaddr, uint32_t baddr, uint32_t b2addr) {
    #pragma unroll
    for (int k = 0; k < 12; k++) {
        uint32_t ah0[4], ah1[4], bh[4], b2[2];
        ldsm_x4(ah0, aaddr);
        ldsm_x4(ah1, aaddr + 16 * AP);
        ldsm_x4(bh, baddr);
        ldsm_x2(b2, b2addr);
        mma6(acc, ah0, ah1, bh, b2);
        aaddr += 32; baddr += 32; b2addr += 32;
    }
}

__device__ __forceinline__ void stage_chunk(uint32_t sb, int c, int tid) {
    const char* src = g_wblob + (size_t)c * 38400;
    #pragma unroll 1
    for (int i = tid; i < 2400; i += NTHREADS) {
        asm volatile("cp.async.cg.shared.global [%0], [%1], 16;"
                     :: "r"(sb + B_B + i * 16), "l"(src + (size_t)i * 16));
    }
    asm volatile("cp.async.commit_group;" ::: "memory");
}
#define CPWAIT() asm volatile("cp.async.wait_group 0;" ::: "memory")

__global__ void prep_weights(const float* __restrict__ qkv_w, const float* __restrict__ proj_w) {
    int idx = blockIdx.x * 256 + threadIdx.x;      // < 8*96*96 = 73728
    int c  = idx / 9216;
    int r  = idx - c * 9216;
    int j  = r / 96, kp = r - (r / 96) * 96;
    int grow = (c < 6) ? ((j >> 5) * 192 + c * 32 + (j & 31)) : ((c - 6) * 96 + j);
    const float2* src = (c < 6) ? (const float2*)qkv_w : (const float2*)proj_w;
    float2 v = src[(size_t)grow * 96 + kp];
    *(__half2*)(g_wblob + (size_t)c * 38400 + j * AP + kp * 4) =
        __floats2half2_rn(v.x, v.y);
}

__global__ void __launch_bounds__(NTHREADS, 2)
wmsa_hmma(const float* __restrict__ x,
          const float* __restrict__ qkv_b,
          const float* __restrict__ proj_b,
          const float* __restrict__ rpe_table,
          const int*   __restrict__ rpe_idx,
          float* __restrict__ out)
{
    extern __shared__ __align__(16) char smem[];
    float* sf = (float*)smem;
    const uint32_t sb = smem_u32(smem);
    const int tid  = threadIdx.x;
    const int warp = tid >> 5;
    const int lane = tid & 31;
    const int wm   = warp >> 2;      // 0..1 (rows 32wm..32wm+31)
    const int wn   = warp & 3;       // 24-col slice
    const int bid  = blockIdx.x;     // 1 window

    // ---- preload bias + rpe; zero image pad rows (rows 49..63) ----
    float* sbias = sf + SBIAS_F;
    for (int i = tid; i < 576; i += NTHREADS) sbias[i] = qkv_b[i];
    for (int i = tid; i < 192; i += NTHREADS) sbias[576 + i] = proj_b[i];
    uint8_t* rpi = (uint8_t*)(smem + RPI_B);
    float*   rpt = sf + RPT_F;
    for (int i = tid; i < 49 * 49; i += NTHREADS) rpi[i] = (uint8_t)rpe_idx[i];
    for (int i = tid; i < 169 * 6; i += NTHREADS) rpt[i] = rpe_table[i];
    {
        uint32_t* z1 = (uint32_t*)(smem + QI_B + 49 * 80);
        uint32_t* z2 = (uint32_t*)(smem + KI_B + 49 * 80);
        uint32_t* z3 = (uint32_t*)(smem + VI_B + 49 * 80);
        for (int i = tid; i < 300; i += NTHREADS) { z1[i] = 0u; z2[i] = 0u; z3[i] = 0u; }
    }

    // ---- stage x -> fp16 hi into A ----
    {
        const float2* xg = (const float2*)(x + (size_t)bid * 49 * 192);
        for (int idx = tid; idx < 49 * 96; idx += NTHREADS) {
            int r = idx / 96, kp = idx - (idx / 96) * 96;
            float2 v = xg[idx];
            *(__half2*)(smem + AH_B + r * AP + kp * 4) = __floats2half2_rn(v.x, v.y);
        }
    }
    stage_chunk(sb, 0, tid);

    // ---- GEMM ldmatrix addresses ----
    const uint32_t aaddr = sb + AH_B
        + (uint32_t)(wm * 32 + (lane & 7) + ((lane >> 3) & 1) * 8) * AP
        + (uint32_t)((lane >> 4) * 16);
    const uint32_t baddr = sb + B_B
        + (uint32_t)(wn * 24 + (lane & 7) + ((lane >> 4) & 1) * 8) * AP
        + (uint32_t)(((lane >> 3) & 1) * 16);
    const int l15 = lane & 15;
    const uint32_t b2addr = sb + B_B
        + (uint32_t)(wn * 24 + 16 + (l15 & 7)) * AP
        + (uint32_t)((l15 >> 3) * 16);

    // ---- attention warp geometry ----
    const int mt  = warp & 3;        // m16 tile (rows 16mt..16mt+15)
    const int nh  = warp >> 2;       // dim half 0/1
    const int qr  = lane >> 2;       // quad row
    const int qc  = (lane & 3) * 2;  // quad col base
    const int iA  = mt * 16 + qr;    // row within window (0..63)
    const int iB  = iA + 8;
    const int iAc = (iA < 49 ? iA : 48) * 49;
    const int iBc = (iB < 49 ? iB : 48) * 49;
    const uint32_t qaddr = sb + QI_B
        + (uint32_t)(mt * 16 + (lane & 7) + ((lane >> 3) & 1) * 8) * 80
        + (uint32_t)((lane >> 4) * 16);
    const uint32_t kaddr0 = sb + KI_B
        + (uint32_t)((lane & 7) + (lane >> 4) * 8) * 80
        + (uint32_t)(((lane >> 3) & 1) * 16);
    // V image row-major [key][dim]; .trans ldsm reproduces the VT fragments.
    // tiles: t0 keys 0-7 dims nh*16+0-7, t1 keys 8-15 same dims, t2/t3 dims +8
    const uint32_t viaddr = sb + VI_B
        + (uint32_t)((lane & 7) + ((lane >> 3) & 1) * 8) * 80
        + (uint32_t)(nh * 32 + (lane >> 4) * 16);

    char* aob = g_ao + (size_t)bid * 19600;

    // ================= Phase 1+2: per-head GEMM + HMMA attention =================
    for (int h = 0; h < 6; h++) {
        CPWAIT();
        __syncthreads();                 // B(h) ready; prior attention image-reads done

        float acc[24];
        #pragma unroll
        for (int i = 0; i < 24; i++) acc[i] = 0.f;
        run_gemm1(acc, aaddr, baddr, b2addr);

        // epilogue: q/k -> fp16 images (+bias, q scaled); v -> row-major fp16
        #pragma unroll
        for (int t = 0; t < 2; t++) {
            #pragma unroll
            for (int u = 0; u < 3; u++) {
                int r0e = wm * 32 + t * 16 + (lane >> 2);
                int c   = wn * 24 + u * 8 + (lane & 3) * 2;
                int blk = c >> 5, cc = c & 31;
                float bb0 = sbias[blk * 192 + h * 32 + cc];
                float bb1 = sbias[blk * 192 + h * 32 + cc + 1];
                const float* a = acc + t * 12 + u * 4;
                #pragma unroll
                for (int rr = 0; rr < 2; rr++) {
                    int r = r0e + rr * 8;
                    if (r < 49) {
                        float v0 = a[rr * 2 + 0] + bb0;
                        float v1 = a[rr * 2 + 1] + bb1;
                        if (blk == 0) {
                            *(__half2*)(smem + QI_B + r * 80 + cc * 2) =
                                __floats2half2_rn(v0 * SCALE, v1 * SCALE);
                        } else if (blk == 1) {
                            *(__half2*)(smem + KI_B + r * 80 + cc * 2) =
                                __floats2half2_rn(v0, v1);
                        } else {
                            *(__half2*)(smem + VI_B + r * 80 + cc * 2) =
                                __floats2half2_rn(v0, v1);
                        }
                    }
                }
            }
        }
        __syncthreads();                 // gemm B-reads + image writes done

        stage_chunk(sb, h + 1, tid);     // prefetch next chunk under attention

        // ---- S = Q K^T (fragments) ----
        float s[7][4];
        #pragma unroll
        for (int i = 0; i < 7; i++) { s[i][0] = s[i][1] = s[i][2] = s[i][3] = 0.f; }
        uint32_t a0[4], a1[4];
        ldsm_x4(a0, qaddr);
        ldsm_x4(a1, qaddr + 32);
        #pragma unroll
        for (int t16 = 0; t16 < 4; t16++) {
            uint32_t b0[4], b1[4];
            uint32_t ka = kaddr0 + (uint32_t)(t16 * 16) * 80;
            ldsm_x4(b0, ka);
            ldsm_x4(b1, ka + 32);
            mma_step(s[2 * t16], a0, b0 + 0);
            mma_step(s[2 * t16], a1, b1 + 0);
            if (t16 < 3) {
                mma_step(s[2 * t16 + 1], a0, b0 + 2);
                mma_step(s[2 * t16 + 1], a1, b1 + 2);
            }
        }

        // ---- bias + mask + softmax in fragments ----
        float mx0 = -1e30f, mx1 = -1e30f;
        #pragma unroll
        for (int t = 0; t < 7; t++) {
            int c0 = t * 8 + qc, c1 = c0 + 1;
            if (c0 < 49) { s[t][0] += rpt[rpi[iAc + c0] * 6 + h]; s[t][2] += rpt[rpi[iBc + c0] * 6 + h]; }
            else         { s[t][0] = -1e30f; s[t][2] = -1e30f; }
            if (c1 < 49) { s[t][1] += rpt[rpi[iAc + c1] * 6 + h]; s[t][3] += rpt[rpi[iBc + c1] * 6 + h]; }
            else         { s[t][1] = -1e30f; s[t][3] = -1e30f; }
            mx0 = fmaxf(mx0, fmaxf(s[t][0], s[t][1]));
            mx1 = fmaxf(mx1, fmaxf(s[t][2], s[t][3]));
        }
        mx0 = fmaxf(mx0, __shfl_xor_sync(0xffffffffu, mx0, 1));
        mx0 = fmaxf(mx0, __shfl_xor_sync(0xffffffffu, mx0, 2));
        mx1 = fmaxf(mx1, __shfl_xor_sync(0xffffffffu, mx1, 1));
        mx1 = fmaxf(mx1, __shfl_xor_sync(0xffffffffu, mx1, 2));
        float sm0 = 0.f, sm1 = 0.f;
        #pragma unroll
        for (int t = 0; t < 7; t++) {
            s[t][0] = __expf(s[t][0] - mx0); s[t][1] = __expf(s[t][1] - mx0);
            s[t][2] = __expf(s[t][2] - mx1); s[t][3] = __expf(s[t][3] - mx1);
            sm0 += s[t][0] + s[t][1];
            sm1 += s[t][2] + s[t][3];
        }
        sm0 += __shfl_xor_sync(0xffffffffu, sm0, 1);
        sm0 += __shfl_xor_sync(0xffffffffu, sm0, 2);
        sm1 += __shfl_xor_sync(0xffffffffu, sm1, 1);
        sm1 += __shfl_xor_sync(0xffffffffu, sm1, 2);
        float iv0 = 1.0f / sm0, iv1 = 1.0f / sm1;

        // ---- P fragments (hi/lo), accumulator layout == A-fragment layout ----
        uint32_t phi[4][4], plo[4][4];
        #pragma unroll
        for (int kc = 0; kc < 4; kc++) {
            #pragma unroll
            for (int h2i = 0; h2i < 4; h2i++) {
                int t = 2 * kc + (h2i >> 1);
                int rsel = (h2i & 1) * 2;
                float p0, p1;
                if (t < 7) {
                    float ivx = (h2i & 1) ? iv1 : iv0;
                    p0 = s[t][rsel + 0] * ivx;
                    p1 = s[t][rsel + 1] * ivx;
                } else { p0 = 0.f; p1 = 0.f; }
                __half hp0 = __float2half_rn(p0), hp1 = __float2half_rn(p1);
                phi[kc][h2i] = pack_h2(hp0, hp1);
                plo[kc][h2i] = pack_h2(__float2half_rn(p0 - __half2float(hp0)),
                                       __float2half_rn(p1 - __half2float(hp1)));
            }
        }

        // ---- PV: 2-pass (Phi + Plo) * Vhi via trans ldsm ----
        float o0[4] = {0.f, 0.f, 0.f, 0.f};
        float o1[4] = {0.f, 0.f, 0.f, 0.f};
        #pragma unroll
        for (int kc = 0; kc < 4; kc++) {
            uint32_t vh[4];
            ldsm_x4_trans(vh, viaddr + (uint32_t)(kc * 16) * 80);
            mma_step(o0, phi[kc], vh + 0);
            mma_step(o1, phi[kc], vh + 2);
            mma_step(o0, plo[kc], vh + 0);
            mma_step(o1, plo[kc], vh + 2);
        }

        // ---- store ao rows as fp16 in A-image layout ----
        {
            int dn = h * 32 + nh * 16 + qc;
            if (iA < 49) {
                *(__half2*)(aob + iA * AP + dn * 2)      = __floats2half2_rn(o0[0], o0[1]);
                *(__half2*)(aob + iA * AP + dn * 2 + 16) = __floats2half2_rn(o1[0], o1[1]);
            }
            if (iB < 49) {
                *(__half2*)(aob + iB * AP + dn * 2)      = __floats2half2_rn(o0[2], o0[3]);
                *(__half2*)(aob + iB * AP + dn * 2 + 16) = __floats2half2_rn(o1[2], o1[3]);
            }
        }
    }
    __syncthreads();   // all ao writes done

    // ---- stage A for phase 3: cp.async the pre-formatted ao blob ----
    {
        #pragma unroll 1
        for (int i = tid; i < 1225; i += NTHREADS) {
            asm volatile("cp.async.cg.shared.global [%0], [%1], 16;"
                         :: "r"(sb + AH_B + i * 16), "l"(aob + (size_t)i * 16));
        }
        asm volatile("cp.async.commit_group;" ::: "memory");
    }

    // ================= Phase 3: out = ao @ proj_w^T + b =================
    for (int s2 = 0; s2 < 2; s2++) {
        CPWAIT();
        __syncthreads();

        float acc[24];
        #pragma unroll
        for (int i = 0; i < 24; i++) acc[i] = 0.f;
        run_gemm1(acc, aaddr, baddr, b2addr);
        __syncthreads();
        if (s2 == 0) stage_chunk(sb, 7, tid);

        #pragma unroll
        for (int t = 0; t < 2; t++) {
            #pragma unroll
            for (int u = 0; u < 3; u++) {
                int r0e = wm * 32 + t * 16 + (lane >> 2);
                int c   = wn * 24 + u * 8 + (lane & 3) * 2;
                int gcol = s2 * 96 + c;
                float bb0 = sbias[576 + gcol];
                float bb1 = sbias[576 + gcol + 1];
                const float* a = acc + t * 12 + u * 4;
                #pragma unroll
                for (int rr = 0; rr < 2; rr++) {
                    int r = r0e + rr * 8;
                    if (r < 49) {
                        float2 v = make_float2(a[rr * 2 + 0] + bb0, a[rr * 2 + 1] + bb1);
                        *(float2*)(out + ((size_t)bid * 49 + r) * 192 + gcol) = v;
                    }
                }
            }
        }
    }
}

extern "C" void kernel_launch(void* const* d_in, const int* in_sizes, int n_in,
                              void* d_out, int out_size)
{
    const float* x         = (const float*)d_in[0];
    const float* qkv_w     = (const float*)d_in[1];
    const float* qkv_b     = (const float*)d_in[2];
    const float* proj_w    = (const float*)d_in[3];
    const float* proj_b    = (const float*)d_in[4];
    const float* rpe_table = (const float*)d_in[5];
    const int*   rpe_idx   = (const int*)d_in[6];
    float* out = (float*)d_out;

    prep_weights<<<288, 256>>>(qkv_w, proj_w);

    cudaFuncSetAttribute(wmsa_hmma,
                         cudaFuncAttributeMaxDynamicSharedMemorySize, SMEM_TOTAL);
    wmsa_hmma<<<4096, NTHREADS, SMEM_TOTAL>>>(
        x, qkv_b, proj_b, rpe_table, rpe_idx, out);
}